// round 3
// baseline (speedup 1.0000x reference)
#include <cuda_runtime.h>
#include <math.h>

// ---------------- problem constants ----------------
#define NIMG   4096          // B*S = 32*128
#define BATCH  32
#define SEQ    128
#define MAPW   24
#define GRIDC_P 25           // padded channel stride in smem
#define C1_HO 23
#define C1_IMG (23*23*16)    // 8464
#define C2_HO 22
#define C2_IMG (22*22*32)    // 15488
#define C3_HO 21
#define FEATD (21*21*64)     // 28224
#define G3    192            // 3*RNN_D
#define RNN_D 64

// GEMM tiling
#define BK 32
#define KSPLIT 3
#define KPART (FEATD/KSPLIT)     // 9408
#define NKITER (KPART/BK)        // 294
#define ASTR 68                  // natural A [k][m] stride (floats)
#define BSTRD 132                // duplicated B [k][2n] stride (floats)

// ---------------- packed f32x2 helpers ----------------
typedef unsigned long long u64t;
__device__ __forceinline__ u64t pk2(float lo, float hi) {
    u64t r; asm("mov.b64 %0, {%1,%2};" : "=l"(r) : "f"(lo), "f"(hi)); return r;
}
__device__ __forceinline__ void upk2(float& lo, float& hi, u64t v) {
    asm("mov.b64 {%0,%1}, %2;" : "=f"(lo), "=f"(hi) : "l"(v));
}
__device__ __forceinline__ void fma2(u64t& d, u64t a, u64t b) {
    asm("fma.rn.f32x2 %0, %1, %2, %0;" : "+l"(d) : "l"(a), "l"(b));
}

// ---------------- scratch (device globals; no allocations allowed) -------
__device__ float g_c1[(size_t)NIMG * C1_IMG];
__device__ float g_c2[(size_t)NIMG * C2_IMG];
__device__ float g_feat[(size_t)NIMG * FEATD];
__device__ float g_igp[KSPLIT][(size_t)NIMG * G3];
__device__ float g_allh[(size_t)NIMG * RNN_D];
__device__ unsigned char g_um8[BATCH*SEQ*2*16];
__device__ unsigned char g_rm8[BATCH*SEQ*6];
__device__ int g_maskkind;   // 0=int32, 1=bool8, 2=float32

// ---------------- mask dtype detection ----------------
__global__ void k_detect(const unsigned char* __restrict__ p, int count) {
    __shared__ int sHi, s80;
    if (threadIdx.x == 0) { sHi = 0; s80 = 0; }
    __syncthreads();
    int hi = 0, b80 = 0;
    for (int i = threadIdx.x; i < count; i += blockDim.x) {
        unsigned char v = p[i];
        if ((i & 3) != 0 && v) hi = 1;
        if ((i & 3) == 2 && v == 0x80) b80 = 1;
    }
    if (hi)  sHi = 1;
    if (b80) s80 = 1;
    __syncthreads();
    if (threadIdx.x == 0) g_maskkind = (!sHi) ? 0 : (s80 ? 2 : 1);
}

__global__ void k_expand(const void* __restrict__ um, const void* __restrict__ rm) {
    int kind = g_maskkind;
    int i = blockIdx.x * blockDim.x + threadIdx.x;
    if (i < BATCH*SEQ*2*16) {
        unsigned char v;
        if (kind == 0)      v = (((const int*)um)[i] != 0);
        else if (kind == 1) v = (((const unsigned char*)um)[i] != 0);
        else                v = (((const float*)um)[i] != 0.f);
        g_um8[i] = v;
    }
    if (i < BATCH*SEQ*6) {
        unsigned char v;
        if (kind == 0)      v = (((const int*)rm)[i] != 0);
        else if (kind == 1) v = (((const unsigned char*)rm)[i] != 0);
        else                v = (((const float*)rm)[i] != 0.f);
        g_rm8[i] = v;
    }
}

// ---------------- fused grid build + conv1 ----------------
__global__ void __launch_bounds__(256) k_grid_conv1(
    const int* __restrict__ positions, const int* __restrict__ tile_type,
    const int* __restrict__ relic_positions, const float* __restrict__ reward,
    const float* __restrict__ emb_tile, const float* __restrict__ emb_unit,
    const float* __restrict__ w1, const float* __restrict__ b1)
{
    extern __shared__ float sm[];
    float* sg = sm;                 // 576*25 = 14400 floats
    float* sw = sm + 576*GRIDC_P;   // 1536 floats, 57600B offset (16B aligned)
    __shared__ int   spos[2][16][2];
    __shared__ unsigned char sum_[2][16];
    __shared__ int   srpos[6][2];
    __shared__ unsigned char srm[6];
    __shared__ float semb_u[128];
    __shared__ float semb_t[12];
    __shared__ u64t  sbp[8];

    int img = blockIdx.x;
    int tid = threadIdx.x;

    if (tid < 64)  ((int*)spos)[tid] = positions[(size_t)img*64 + tid];
    if (tid < 32)  ((unsigned char*)sum_)[tid] = g_um8[img*32 + tid];
    if (tid < 12)  ((int*)srpos)[tid] = relic_positions[(size_t)img*12 + tid];
    if (tid < 6)   srm[tid] = g_rm8[img*6 + tid];
    if (tid < 12)  semb_t[tid] = emb_tile[tid];
    if (tid < 128) semb_u[tid] = emb_unit[tid];
    if (tid < 8)   sbp[tid] = pk2(b1[2*tid], b1[2*tid+1]);
    for (int i = tid; i < 1536; i += 256) sw[i] = w1[i];
    float rw = reward[img];
    __syncthreads();

    // build grid (24 channels, padded stride 25)
    for (int p = tid; p < 576; p += 256) {
        int y = p / MAPW, x = p - y * MAPW;
        float e[16];
        #pragma unroll
        for (int j = 0; j < 16; j++) e[j] = 0.f;
        float cnt0 = 0.f, cnt1 = 0.f;
        #pragma unroll
        for (int t = 0; t < 2; t++) {
            #pragma unroll
            for (int u = 0; u < 16; u++) {
                if (sum_[t][u] && spos[t][u][0] == y && spos[t][u][1] == x) {
                    if (t == 0) cnt0 += 1.f; else cnt1 += 1.f;
                    #pragma unroll
                    for (int j = 0; j < 8; j++) e[t*8 + j] += semb_u[u*8 + j];
                }
            }
        }
        float rc = 0.f;
        #pragma unroll
        for (int r = 0; r < 6; r++)
            if (srm[r] && srpos[r][0] == y && srpos[r][1] == x) rc += 1.f;
        int tt = tile_type[(size_t)img*576 + p];
        float* gp = &sg[p * GRIDC_P];
        gp[0] = semb_t[tt*4+0]; gp[1] = semb_t[tt*4+1];
        gp[2] = semb_t[tt*4+2]; gp[3] = semb_t[tt*4+3];
        gp[4] = cnt0 * 0.0625f; gp[5] = cnt1 * 0.0625f;
        #pragma unroll
        for (int j = 0; j < 16; j++) gp[6 + j] = e[j];
        gp[22] = rc; gp[23] = rw;
    }
    __syncthreads();

    // conv1: 24ch -> 16ch, 2x2 valid, FFMA2 accumulators (8 pairs)
    for (int p = tid; p < C1_HO*C1_HO; p += 256) {
        int y = p / C1_HO, x = p - y * C1_HO;
        u64t acc[8];
        #pragma unroll
        for (int c = 0; c < 8; c++) acc[c] = sbp[c];
        for (int k = 0; k < 4; k++) {
            int ky = k >> 1, kx = k & 1;
            const float* row = &sg[((y+ky)*MAPW + (x+kx)) * GRIDC_P];
            #pragma unroll 6
            for (int ci = 0; ci < 24; ci++) {
                float v = row[ci];
                u64t vd = pk2(v, v);
                const ulonglong2* wp = (const ulonglong2*)&sw[(k*24 + ci)*16];
                #pragma unroll
                for (int g = 0; g < 4; g++) {
                    ulonglong2 w = wp[g];
                    fma2(acc[2*g],   vd, w.x);
                    fma2(acc[2*g+1], vd, w.y);
                }
            }
        }
        float4* op = (float4*)&g_c1[(size_t)img*C1_IMG + p*16];
        #pragma unroll
        for (int g = 0; g < 4; g++) {
            float a0,a1,a2,a3;
            upk2(a0,a1,acc[2*g]); upk2(a2,a3,acc[2*g+1]);
            float4 v;
            v.x = fmaxf(a0, 0.f); v.y = fmaxf(a1, 0.f);
            v.z = fmaxf(a2, 0.f); v.w = fmaxf(a3, 0.f);
            op[g] = v;
        }
    }
}

// ---------------- conv2: 16ch 23x23 -> 32ch 22x22 ----------------
__global__ void __launch_bounds__(256) k_conv2(const float* __restrict__ w2,
                                               const float* __restrict__ b2)
{
    extern __shared__ float sm[];
    float* si = sm;            // 529*17 = 8993 used, region padded to 9000
    float* sw = sm + 9000;     // 36000B offset -> 16B aligned
    __shared__ u64t sbp[16];
    int img = blockIdx.x, tid = threadIdx.x;
    const float* in = &g_c1[(size_t)img*C1_IMG];
    for (int i = tid; i < C1_IMG; i += 256) si[(i >> 4)*17 + (i & 15)] = in[i];
    for (int i = tid; i < 2048; i += 256) sw[i] = w2[i];
    if (tid < 16) sbp[tid] = pk2(b2[2*tid], b2[2*tid+1]);
    __syncthreads();

    for (int p = tid; p < C2_HO*C2_HO; p += 256) {
        int y = p / C2_HO, x = p - y * C2_HO;
        u64t acc[16];
        #pragma unroll
        for (int c = 0; c < 16; c++) acc[c] = sbp[c];
        for (int k = 0; k < 4; k++) {
            int ky = k >> 1, kx = k & 1;
            const float* row = &si[((y+ky)*C1_HO + (x+kx))*17];
            #pragma unroll 8
            for (int ci = 0; ci < 16; ci++) {
                float v = row[ci];
                u64t vd = pk2(v, v);
                const ulonglong2* wp = (const ulonglong2*)&sw[(k*16 + ci)*32];
                #pragma unroll
                for (int g = 0; g < 8; g++) {
                    ulonglong2 w = wp[g];
                    fma2(acc[2*g],   vd, w.x);
                    fma2(acc[2*g+1], vd, w.y);
                }
            }
        }
        float4* op = (float4*)&g_c2[(size_t)img*C2_IMG + p*32];
        #pragma unroll
        for (int g = 0; g < 8; g++) {
            float a0,a1,a2,a3;
            upk2(a0,a1,acc[2*g]); upk2(a2,a3,acc[2*g+1]);
            float4 v;
            v.x = fmaxf(a0, 0.f); v.y = fmaxf(a1, 0.f);
            v.z = fmaxf(a2, 0.f); v.w = fmaxf(a3, 0.f);
            op[g] = v;
        }
    }
}

// ---------------- conv3: 32ch 22x22 -> 64ch 21x21 ----------------
__global__ void __launch_bounds__(256, 2) k_conv3(const float* __restrict__ w3,
                                                  const float* __restrict__ b3)
{
    extern __shared__ float sm[];
    float* si = sm;                // 484*33 = 15972 floats (63888B, 16B aligned)
    float* sw = sm + 484*33;       // 8192 floats
    __shared__ u64t sbp[32];
    int img = blockIdx.x, tid = threadIdx.x;
    const float* in = &g_c2[(size_t)img*C2_IMG];
    for (int i = tid; i < C2_IMG; i += 256) si[(i >> 5)*33 + (i & 31)] = in[i];
    for (int i = tid; i < 8192; i += 256) sw[i] = w3[i];
    if (tid < 32) sbp[tid] = pk2(b3[2*tid], b3[2*tid+1]);
    __syncthreads();

    for (int p = tid; p < C3_HO*C3_HO; p += 256) {
        int y = p / C3_HO, x = p - y * C3_HO;
        u64t acc[32];
        #pragma unroll
        for (int c = 0; c < 32; c++) acc[c] = sbp[c];
        for (int k = 0; k < 4; k++) {
            int ky = k >> 1, kx = k & 1;
            const float* row = &si[((y+ky)*C2_HO + (x+kx))*33];
            #pragma unroll 4
            for (int ci = 0; ci < 32; ci++) {
                float v = row[ci];
                u64t vd = pk2(v, v);
                const ulonglong2* wp = (const ulonglong2*)&sw[(k*32 + ci)*64];
                #pragma unroll
                for (int g = 0; g < 16; g++) {
                    ulonglong2 w = wp[g];
                    fma2(acc[2*g],   vd, w.x);
                    fma2(acc[2*g+1], vd, w.y);
                }
            }
        }
        float4* op = (float4*)&g_feat[(size_t)img*FEATD + p*64];
        #pragma unroll
        for (int g = 0; g < 16; g++) {
            float a0,a1,a2,a3;
            upk2(a0,a1,acc[2*g]); upk2(a2,a3,acc[2*g+1]);
            float4 v;
            v.x = fmaxf(a0, 0.f); v.y = fmaxf(a1, 0.f);
            v.z = fmaxf(a2, 0.f); v.w = fmaxf(a3, 0.f);
            op[g] = v;
        }
    }
}

// ---------------- big GEMM: IG = feat @ Wi^T (split-K=3 partials) ---------
// A tile natural transposed [k][m] (conflict-free LDS.128, FFMA2-ready m-pairs);
// B tile duplicated (b,b) pairs, ty-indexed -> warp-broadcast reads.
__global__ void __launch_bounds__(256) k_gemm(const float* __restrict__ Wi)
{
    extern __shared__ float sm[];
    float* As  = sm;                  // 2 bufs * 32 * 68 = 4352 floats
    float* Bsd = sm + 2*BK*ASTR;      // 17408B offset (16B aligned); 2*32*132 = 8448 floats
    int tid = threadIdx.x;
    int m0 = blockIdx.x * 64, n0 = blockIdx.y * 64, z = blockIdx.z;
    const float* Aptr = g_feat + (size_t)m0*FEATD + (size_t)z*KPART;
    const float* Bptr = Wi     + (size_t)n0*FEATD + (size_t)z*KPART;
    int row = tid >> 3, cq = tid & 7;   // fill mapping: 32 rows x 8 float4 cols
    int tx = tid & 15, ty = tid >> 4;   // compute mapping: 16 x 16

    float4 pa0, pa1, pb0, pb1;
    u64t acc[4][2];                     // [n j][m half]
    #pragma unroll
    for (int j = 0; j < 4; j++) { acc[j][0] = 0ull; acc[j][1] = 0ull; }

    // prologue: load + store tile 0
    pa0 = *(const float4*)(Aptr + (size_t)row*FEATD + cq*4);
    pa1 = *(const float4*)(Aptr + (size_t)(row+32)*FEATD + cq*4);
    pb0 = *(const float4*)(Bptr + (size_t)row*FEATD + cq*4);
    pb1 = *(const float4*)(Bptr + (size_t)(row+32)*FEATD + cq*4);
    {
        float av0[4] = {pa0.x, pa0.y, pa0.z, pa0.w};
        float av1[4] = {pa1.x, pa1.y, pa1.z, pa1.w};
        float bv0[4] = {pb0.x, pb0.y, pb0.z, pb0.w};
        float bv1[4] = {pb1.x, pb1.y, pb1.z, pb1.w};
        #pragma unroll
        for (int j = 0; j < 4; j++) {
            int c = cq*4 + j;
            As[c*ASTR + row]       = av0[j];
            As[c*ASTR + row + 32]  = av1[j];
            *(float2*)&Bsd[c*BSTRD + 2*row]      = make_float2(bv0[j], bv0[j]);
            *(float2*)&Bsd[c*BSTRD + 2*(row+32)] = make_float2(bv1[j], bv1[j]);
        }
    }
    __syncthreads();

    for (int kt = 0; kt < NKITER; kt++) {
        int cur = kt & 1;
        if (kt + 1 < NKITER) {
            const float* ap = Aptr + (size_t)(kt+1)*BK;
            const float* bp = Bptr + (size_t)(kt+1)*BK;
            pa0 = *(const float4*)(ap + (size_t)row*FEATD + cq*4);
            pa1 = *(const float4*)(ap + (size_t)(row+32)*FEATD + cq*4);
            pb0 = *(const float4*)(bp + (size_t)row*FEATD + cq*4);
            pb1 = *(const float4*)(bp + (size_t)(row+32)*FEATD + cq*4);
        }
        const float* As_c  = As  + cur*BK*ASTR;
        const float* Bsd_c = Bsd + cur*BK*BSTRD;
        #pragma unroll
        for (int kk = 0; kk < BK; kk++) {
            ulonglong2 av  = *(const ulonglong2*)&As_c[kk*ASTR + tx*4];
            ulonglong2 bv0_ = *(const ulonglong2*)&Bsd_c[kk*BSTRD + ty*8];
            ulonglong2 bv1_ = *(const ulonglong2*)&Bsd_c[kk*BSTRD + ty*8 + 4];
            fma2(acc[0][0], av.x, bv0_.x); fma2(acc[0][1], av.y, bv0_.x);
            fma2(acc[1][0], av.x, bv0_.y); fma2(acc[1][1], av.y, bv0_.y);
            fma2(acc[2][0], av.x, bv1_.x); fma2(acc[2][1], av.y, bv1_.x);
            fma2(acc[3][0], av.x, bv1_.y); fma2(acc[3][1], av.y, bv1_.y);
        }
        if (kt + 1 < NKITER) {
            int nxt = cur ^ 1;
            float* As_n  = As  + nxt*BK*ASTR;
            float* Bsd_n = Bsd + nxt*BK*BSTRD;
            float av0[4] = {pa0.x, pa0.y, pa0.z, pa0.w};
            float av1[4] = {pa1.x, pa1.y, pa1.z, pa1.w};
            float bv0[4] = {pb0.x, pb0.y, pb0.z, pb0.w};
            float bv1[4] = {pb1.x, pb1.y, pb1.z, pb1.w};
            #pragma unroll
            for (int j = 0; j < 4; j++) {
                int c = cq*4 + j;
                As_n[c*ASTR + row]       = av0[j];
                As_n[c*ASTR + row + 32]  = av1[j];
                *(float2*)&Bsd_n[c*BSTRD + 2*row]      = make_float2(bv0[j], bv0[j]);
                *(float2*)&Bsd_n[c*BSTRD + 2*(row+32)] = make_float2(bv1[j], bv1[j]);
            }
            __syncthreads();
        }
    }

    // epilogue: acc[j][h] lanes are m = tx*4 + 2h (+1); n = n0 + ty*4 + j
    float o[4][4];
    #pragma unroll
    for (int j = 0; j < 4; j++) {
        upk2(o[0][j], o[1][j], acc[j][0]);
        upk2(o[2][j], o[3][j], acc[j][1]);
    }
    float* op = &g_igp[z][0];
    #pragma unroll
    for (int i = 0; i < 4; i++) {
        int m = m0 + tx*4 + i;
        *(float4*)&op[(size_t)m*G3 + n0 + ty*4] =
            make_float4(o[i][0], o[i][1], o[i][2], o[i][3]);
    }
}

// ---------------- GRU scan: 32 blocks (one per batch row) ----------------
__global__ void __launch_bounds__(192) k_scan(
    const float* __restrict__ Wh, const float* __restrict__ bi,
    const float* __restrict__ bn, const float* __restrict__ h0,
    float* __restrict__ out_hidden)
{
    extern __shared__ float sWhT[];   // 64*192, WhT[d*192+n]
    __shared__ float sh[64], shg[192], sig[192], sbi[192], sbn[64];
    int b = blockIdx.x, tid = threadIdx.x;
    for (int i = tid; i < 64*G3; i += 192) {
        int d = i / G3, n = i - d*G3;
        sWhT[i] = Wh[n*64 + d];
    }
    sbi[tid] = bi[tid];
    if (tid < 64) { sbn[tid] = bn[tid]; sh[tid] = h0[b*64 + tid]; }
    __syncthreads();

    for (int t = 0; t < SEQ; t++) {
        size_t idx = (size_t)(b*SEQ + t)*G3 + tid;
        float ps = g_igp[0][idx] + g_igp[1][idx] + g_igp[2][idx];
        float acc = 0.f;
        #pragma unroll
        for (int d = 0; d < 64; d++) acc = fmaf(sh[d], sWhT[d*G3 + tid], acc);
        shg[tid] = acc;
        sig[tid] = ps + sbi[tid];
        __syncthreads();
        if (tid < 64) {
            float r  = 1.f / (1.f + expf(-(sig[tid]       + shg[tid])));
            float zz = 1.f / (1.f + expf(-(sig[64 + tid]  + shg[64 + tid])));
            float nn = tanhf(sig[128 + tid] + r * (shg[128 + tid] + sbn[tid]));
            float h  = (1.f - zz) * nn + zz * sh[tid];
            sh[tid] = h;
            g_allh[(size_t)(b*SEQ + t)*64 + tid] = h;
        }
        __syncthreads();
    }
    if (tid < 64) out_hidden[b*64 + tid] = sh[tid];
}

// ---------------- output heads ----------------
__global__ void __launch_bounds__(128) k_head(
    const float* __restrict__ Wa1, const float* __restrict__ ba1,
    const float* __restrict__ Wa2, const float* __restrict__ ba2,
    const float* __restrict__ Wc1, const float* __restrict__ bc1,
    const float* __restrict__ Wc2, const float* __restrict__ bc2,
    float* __restrict__ out_logits, float* __restrict__ out_values)
{
    __shared__ float sh[64], sa[64], sc[64];
    int row = blockIdx.x, tid = threadIdx.x;
    if (tid < 64) sh[tid] = g_allh[(size_t)row*64 + tid];
    __syncthreads();
    if (tid < 64) {
        float a = ba1[tid], c = bc1[tid];
        #pragma unroll
        for (int d = 0; d < 64; d++) {
            float h = sh[d];
            a = fmaf(h, Wa1[d*64 + tid], a);
            c = fmaf(h, Wc1[d*64 + tid], c);
        }
        sa[tid] = tanhf(a);
        sc[tid] = tanhf(c);
    }
    __syncthreads();
    if (tid < 96) {
        float l = ba2[tid];
        #pragma unroll
        for (int j = 0; j < 64; j++) l = fmaf(sa[j], Wa2[j*96 + tid], l);
        out_logits[(size_t)row*96 + tid] = l;
    } else {
        int d = tid - 96;
        float v = sc[d]*Wc2[d] + sc[d+32]*Wc2[d+32];
        #pragma unroll
        for (int o = 16; o > 0; o >>= 1) v += __shfl_xor_sync(0xffffffffu, v, o);
        if (d == 0) out_values[row] = v + bc2[0];
    }
}

// ---------------- launch ----------------
extern "C" void kernel_launch(void* const* d_in, const int* in_sizes, int n_in,
                              void* d_out, int out_size)
{
    const int*   positions       = (const int*)  d_in[0];
    const void*  units_mask      =               d_in[1];
    const int*   tile_type       = (const int*)  d_in[2];
    const int*   relic_positions = (const int*)  d_in[3];
    const void*  relic_mask      =               d_in[4];
    const float* reward          = (const float*)d_in[5];
    const float* hidden          = (const float*)d_in[6];
    const float* emb_tile        = (const float*)d_in[7];
    const float* emb_unit        = (const float*)d_in[8];
    const float* w1 = (const float*)d_in[9];
    const float* b1 = (const float*)d_in[10];
    const float* w2 = (const float*)d_in[11];
    const float* b2 = (const float*)d_in[12];
    const float* w3 = (const float*)d_in[13];
    const float* b3 = (const float*)d_in[14];
    const float* Wi = (const float*)d_in[15];
    const float* Wh = (const float*)d_in[16];
    const float* bi = (const float*)d_in[17];
    const float* bn = (const float*)d_in[18];
    const float* Wa1 = (const float*)d_in[19];
    const float* ba1 = (const float*)d_in[20];
    const float* Wa2 = (const float*)d_in[21];
    const float* ba2 = (const float*)d_in[22];
    const float* Wc1 = (const float*)d_in[23];
    const float* bc1 = (const float*)d_in[24];
    const float* Wc2 = (const float*)d_in[25];
    const float* bc2 = (const float*)d_in[26];

    float* out        = (float*)d_out;
    float* out_logits = out;                       // 4096*96
    float* out_values = out + 393216;              // 4096
    float* out_hidden = out + 393216 + 4096;       // 2048

    const int smem_gc1  = (576*GRIDC_P + 1536) * 4;         // 63744
    const int smem_c2   = (9000 + 2048) * 4;                // 44192
    const int smem_c3   = (484*33 + 8192) * 4;              // 96656
    const int smem_gemm = (2*BK*ASTR + 2*BK*BSTRD) * 4;     // 51200
    const int smem_scan = 64*G3*4;                          // 49152

    cudaFuncSetAttribute(k_grid_conv1, cudaFuncAttributeMaxDynamicSharedMemorySize, smem_gc1);
    cudaFuncSetAttribute(k_conv2,      cudaFuncAttributeMaxDynamicSharedMemorySize, smem_c2);
    cudaFuncSetAttribute(k_conv3,      cudaFuncAttributeMaxDynamicSharedMemorySize, smem_c3);
    cudaFuncSetAttribute(k_gemm,       cudaFuncAttributeMaxDynamicSharedMemorySize, smem_gemm);
    cudaFuncSetAttribute(k_scan,       cudaFuncAttributeMaxDynamicSharedMemorySize, smem_scan);

    k_detect<<<1, 256>>>((const unsigned char*)units_mask, BATCH*SEQ*2*16);
    k_expand<<<(BATCH*SEQ*2*16 + 255)/256, 256>>>(units_mask, relic_mask);

    k_grid_conv1<<<NIMG, 256, smem_gc1>>>(positions, tile_type, relic_positions,
                                          reward, emb_tile, emb_unit, w1, b1);
    k_conv2<<<NIMG, 256, smem_c2>>>(w2, b2);
    k_conv3<<<NIMG, 256, smem_c3>>>(w3, b3);

    dim3 gg(NIMG/64, G3/64, KSPLIT);
    k_gemm<<<gg, 256, smem_gemm>>>(Wi);

    k_scan<<<BATCH, 192, smem_scan>>>(Wh, bi, bn, hidden, out_hidden);
    k_head<<<NIMG, 128>>>(Wa1, ba1, Wa2, ba2, Wc1, bc1, Wc2, bc2,
                          out_logits, out_values);
}

// round 7
// speedup vs baseline: 1.2813x; 1.2813x over previous
#include <cuda_runtime.h>
#include <math.h>

// ---------------- problem constants ----------------
#define NIMG   4096          // B*S = 32*128
#define BATCH  32
#define SEQ    128
#define MAPW   24
#define G1STR  28            // grid smem channel stride (16B-aligned rows)
#define C1_HO 23
#define C1_IMG (23*23*16)    // 8464
#define C2_HO 22
#define C2_IMG (22*22*32)    // 15488
#define C3_HO 21
#define FEATD (21*21*64)     // 28224
#define G3    192            // 3*RNN_D
#define RNN_D 64

// GEMM tiling
#define GBM 128
#define GBN 64
#define GBK 32
#define GMS 132              // smem row stride (floats)
#define KSPLIT 3
#define KPART (FEATD/KSPLIT)     // 9408
#define NKITER (KPART/GBK)       // 294

// ---------------- packed f32x2 helpers ----------------
typedef unsigned long long u64t;
__device__ __forceinline__ u64t pk2(float lo, float hi) {
    u64t r; asm("mov.b64 %0, {%1,%2};" : "=l"(r) : "f"(lo), "f"(hi)); return r;
}
__device__ __forceinline__ void upk2(float& lo, float& hi, u64t v) {
    asm("mov.b64 {%0,%1}, %2;" : "=f"(lo), "=f"(hi) : "l"(v));
}
__device__ __forceinline__ void fma2(u64t& d, u64t a, u64t b) {
    asm("fma.rn.f32x2 %0, %1, %2, %0;" : "+l"(d) : "l"(a), "l"(b));
}

// ---------------- scratch ----------------
__device__ float g_c1[(size_t)NIMG * C1_IMG];
__device__ float g_c2[(size_t)NIMG * C2_IMG];
__device__ float g_feat[(size_t)NIMG * FEATD];
__device__ float g_igp[KSPLIT][(size_t)NIMG * G3];
__device__ float g_allh[(size_t)NIMG * RNN_D];
__device__ unsigned char g_um8[BATCH*SEQ*2*16];
__device__ unsigned char g_rm8[BATCH*SEQ*6];
__device__ int g_maskkind;   // 0=int32, 1=bool8, 2=float32

// ---------------- mask dtype detection ----------------
__global__ void k_detect(const unsigned char* __restrict__ p, int count) {
    __shared__ int sHi, s80;
    if (threadIdx.x == 0) { sHi = 0; s80 = 0; }
    __syncthreads();
    int hi = 0, b80 = 0;
    for (int i = threadIdx.x; i < count; i += blockDim.x) {
        unsigned char v = p[i];
        if ((i & 3) != 0 && v) hi = 1;
        if ((i & 3) == 2 && v == 0x80) b80 = 1;
    }
    if (hi)  sHi = 1;
    if (b80) s80 = 1;
    __syncthreads();
    if (threadIdx.x == 0) g_maskkind = (!sHi) ? 0 : (s80 ? 2 : 1);
}

__global__ void k_expand(const void* __restrict__ um, const void* __restrict__ rm) {
    int kind = g_maskkind;
    int i = blockIdx.x * blockDim.x + threadIdx.x;
    if (i < BATCH*SEQ*2*16) {
        unsigned char v;
        if (kind == 0)      v = (((const int*)um)[i] != 0);
        else if (kind == 1) v = (((const unsigned char*)um)[i] != 0);
        else                v = (((const float*)um)[i] != 0.f);
        g_um8[i] = v;
    }
    if (i < BATCH*SEQ*6) {
        unsigned char v;
        if (kind == 0)      v = (((const int*)rm)[i] != 0);
        else if (kind == 1) v = (((const unsigned char*)rm)[i] != 0);
        else                v = (((const float*)rm)[i] != 0.f);
        g_rm8[i] = v;
    }
}

// ---------------- generic 2x2-VALID conv block (pixel-register-blocked) ----
// Thread computes PX pixels x 16 output channels (group cg).
// si: input [pixel][ch] with stride ISTR (16B-aligned rows).
// sw: weights [(k*CI+ci)][CO_ALL]. Rolled k/q loops keep SASS inside L0 I$.
template<int PX, int NQ, int CO_ALL, int ISTR, int IW, int OW, int NPX>
__device__ __forceinline__ void conv2x2_block(
    const float* __restrict__ si, const float* __restrict__ sw,
    const u64t* bias, float* __restrict__ gout, int cg, int px0, int pxstride)
{
    int pxv[PX]; const float* base[PX];
    #pragma unroll
    for (int p = 0; p < PX; p++) {
        pxv[p] = px0 + p * pxstride;
        int pc = pxv[p] < NPX ? pxv[p] : 0;
        int y = pc / OW, x = pc - y * OW;
        base[p] = si + (y * IW + x) * ISTR;
    }
    u64t acc[PX][8];
    #pragma unroll
    for (int p = 0; p < PX; p++)
        #pragma unroll
        for (int j = 0; j < 8; j++) acc[p][j] = bias[j];

    #pragma unroll 1
    for (int k = 0; k < 4; k++) {
        const int off = ((k >> 1) * IW + (k & 1)) * ISTR;
        #pragma unroll 1
        for (int q = 0; q < NQ; q++) {
            float4 in[PX];
            #pragma unroll
            for (int p = 0; p < PX; p++)
                in[p] = *(const float4*)(base[p] + off + q * 4);
            const float* wbase = &sw[(k * NQ * 4 + q * 4) * CO_ALL + cg * 16];
            #pragma unroll
            for (int cc = 0; cc < 4; cc++) {
                const ulonglong2* wp = (const ulonglong2*)(wbase + cc * CO_ALL);
                ulonglong2 w0 = wp[0], w1 = wp[1], w2 = wp[2], w3 = wp[3];
                #pragma unroll
                for (int p = 0; p < PX; p++) {
                    float v = cc == 0 ? in[p].x : cc == 1 ? in[p].y
                            : cc == 2 ? in[p].z : in[p].w;
                    u64t vd = pk2(v, v);
                    fma2(acc[p][0], vd, w0.x); fma2(acc[p][1], vd, w0.y);
                    fma2(acc[p][2], vd, w1.x); fma2(acc[p][3], vd, w1.y);
                    fma2(acc[p][4], vd, w2.x); fma2(acc[p][5], vd, w2.y);
                    fma2(acc[p][6], vd, w3.x); fma2(acc[p][7], vd, w3.y);
                }
            }
        }
    }
    #pragma unroll
    for (int p = 0; p < PX; p++) {
        if (pxv[p] < NPX) {
            float4* op = (float4*)&gout[(size_t)pxv[p] * CO_ALL + cg * 16];
            #pragma unroll
            for (int g = 0; g < 4; g++) {
                float a0, a1, a2, a3;
                upk2(a0, a1, acc[p][2*g]); upk2(a2, a3, acc[p][2*g+1]);
                float4 v;
                v.x = fmaxf(a0, 0.f); v.y = fmaxf(a1, 0.f);
                v.z = fmaxf(a2, 0.f); v.w = fmaxf(a3, 0.f);
                op[g] = v;
            }
        }
    }
}

// ---------------- fused grid build + conv1 (24ch->16ch) ----------------
__global__ void __launch_bounds__(256) k_grid_conv1(
    const int* __restrict__ positions, const int* __restrict__ tile_type,
    const int* __restrict__ relic_positions, const float* __restrict__ reward,
    const float* __restrict__ emb_tile, const float* __restrict__ emb_unit,
    const float* __restrict__ w1, const float* __restrict__ b1)
{
    extern __shared__ float sm[];
    float* sg = sm;                  // 576*28 = 16128 floats
    float* sw = sm + 576*G1STR;      // 1536 floats (64512B offset, aligned)
    __shared__ int   spos[2][16][2];
    __shared__ unsigned char sum_[2][16];
    __shared__ int   srpos[6][2];
    __shared__ unsigned char srm[6];
    __shared__ float semb_u[128];
    __shared__ float semb_t[12];

    int img = blockIdx.x;
    int tid = threadIdx.x;

    if (tid < 64)  ((int*)spos)[tid] = positions[(size_t)img*64 + tid];
    if (tid < 32)  ((unsigned char*)sum_)[tid] = g_um8[img*32 + tid];
    if (tid < 12)  ((int*)srpos)[tid] = relic_positions[(size_t)img*12 + tid];
    if (tid < 6)   srm[tid] = g_rm8[img*6 + tid];
    if (tid < 12)  semb_t[tid] = emb_tile[tid];
    if (tid < 128) semb_u[tid] = emb_unit[tid];
    for (int i = tid; i < 1536; i += 256) sw[i] = w1[i];
    float rw = reward[img];
    u64t bias[8];
    #pragma unroll
    for (int j = 0; j < 8; j++) bias[j] = pk2(b1[2*j], b1[2*j+1]);
    __syncthreads();

    // build grid (24 channels, padded stride 28)
    for (int p = tid; p < 576; p += 256) {
        int y = p / MAPW, x = p - y * MAPW;
        float e[16];
        #pragma unroll
        for (int j = 0; j < 16; j++) e[j] = 0.f;
        float cnt0 = 0.f, cnt1 = 0.f;
        #pragma unroll
        for (int t = 0; t < 2; t++) {
            #pragma unroll
            for (int u = 0; u < 16; u++) {
                if (sum_[t][u] && spos[t][u][0] == y && spos[t][u][1] == x) {
                    if (t == 0) cnt0 += 1.f; else cnt1 += 1.f;
                    #pragma unroll
                    for (int j = 0; j < 8; j++) e[t*8 + j] += semb_u[u*8 + j];
                }
            }
        }
        float rc = 0.f;
        #pragma unroll
        for (int r = 0; r < 6; r++)
            if (srm[r] && srpos[r][0] == y && srpos[r][1] == x) rc += 1.f;
        int tt = tile_type[(size_t)img*576 + p];
        float* gp = &sg[p * G1STR];
        gp[0] = semb_t[tt*4+0]; gp[1] = semb_t[tt*4+1];
        gp[2] = semb_t[tt*4+2]; gp[3] = semb_t[tt*4+3];
        gp[4] = cnt0 * 0.0625f; gp[5] = cnt1 * 0.0625f;
        #pragma unroll
        for (int j = 0; j < 16; j++) gp[6 + j] = e[j];
        gp[22] = rc; gp[23] = rw;
    }
    __syncthreads();

    // conv1: PX=3 pixels per thread, all 16 out channels
    conv2x2_block<3, 6, 16, G1STR, 24, 23, 529>(
        sg, sw, bias, g_c1 + (size_t)img*C1_IMG, 0, tid, 256);
}

// ---------------- conv2: 16ch 23x23 -> 32ch 22x22 ----------------
#define C2ISTR 20
__global__ void __launch_bounds__(256) k_conv2(const float* __restrict__ w2,
                                               const float* __restrict__ b2)
{
    extern __shared__ float sm[];
    float* si = sm;                // 529*20 = 10580 floats
    float* sw = sm + 529*C2ISTR;   // 2048 floats (42320B offset, aligned)
    int img = blockIdx.x, tid = threadIdx.x;
    const float4* in4 = (const float4*)&g_c1[(size_t)img*C1_IMG];
    for (int i4 = tid; i4 < 529*4; i4 += 256) {
        int px = i4 >> 2, c4 = i4 & 3;
        *(float4*)&si[px*C2ISTR + c4*4] = in4[i4];
    }
    for (int i = tid; i < 2048; i += 256) sw[i] = w2[i];
    int cg = tid >> 7, ps = tid & 127;
    u64t bias[8];
    #pragma unroll
    for (int j = 0; j < 8; j++) bias[j] = pk2(b2[cg*16 + 2*j], b2[cg*16 + 2*j + 1]);
    __syncthreads();

    conv2x2_block<4, 4, 32, C2ISTR, 23, 22, 484>(
        si, sw, bias, g_c2 + (size_t)img*C2_IMG, cg, ps, 128);
}

// ---------------- conv3: 32ch 22x22 -> 64ch 21x21 ----------------
#define C3ISTR 36
__global__ void __launch_bounds__(256) k_conv3(const float* __restrict__ w3,
                                               const float* __restrict__ b3)
{
    extern __shared__ float sm[];
    float* si = sm;                // 484*36 = 17424 floats
    float* sw = sm + 484*C3ISTR;   // 8192 floats (69696B offset, aligned)
    int img = blockIdx.x, tid = threadIdx.x;
    const float4* in4 = (const float4*)&g_c2[(size_t)img*C2_IMG];
    for (int i4 = tid; i4 < 484*8; i4 += 256) {
        int px = i4 >> 3, c4 = i4 & 7;
        *(float4*)&si[px*C3ISTR + c4*4] = in4[i4];
    }
    for (int i = tid; i < 8192; i += 256) sw[i] = w3[i];
    int cg = tid >> 6, ps = tid & 63;
    u64t bias[8];
    #pragma unroll
    for (int j = 0; j < 8; j++) bias[j] = pk2(b3[cg*16 + 2*j], b3[cg*16 + 2*j + 1]);
    __syncthreads();

    float* out = g_feat + (size_t)img*FEATD;
    conv2x2_block<4, 8, 64, C3ISTR, 22, 21, 441>(si, sw, bias, out, cg, ps, 64);
    conv2x2_block<3, 8, 64, C3ISTR, 22, 21, 441>(si, sw, bias, out, cg, 256 + ps, 64);
}

// ---------------- big GEMM: IG = feat @ Wi^T (split-K=3 partials) ---------
// 128 threads, tile 128m x 64n x 32k; thread block 8m x 8n (FFMA2).
// A natural [k][m]; B duplicated (b,b) pairs [k][2n] -> warp-broadcast reads.
__global__ void __launch_bounds__(128, 3) k_gemm(const float* __restrict__ Wi)
{
    extern __shared__ float sm[];
    float* As  = sm;                  // 2 * 32 * 132
    float* Bsd = sm + 2*GBK*GMS;      // 2 * 32 * 132 (33792B offset, aligned)
    int tid = threadIdx.x;
    int m0 = blockIdx.x * GBM, n0 = blockIdx.y * GBN, z = blockIdx.z;
    const float* Aptr = g_feat + (size_t)m0*FEATD + (size_t)z*KPART;
    const float* Bptr = Wi     + (size_t)n0*FEATD + (size_t)z*KPART;

    int tx = tid & 15, ty = tid >> 4;          // compute map (16 x 8)
    int bn_f = tid & 63, bq = (tid >> 6) * 16; // B fill: k base

    float4 pa[8], pb[4];
    u64t acc[8][4];                            // [n][m-chunk]
    #pragma unroll
    for (int j = 0; j < 8; j++)
        #pragma unroll
        for (int c = 0; c < 4; c++) acc[j][c] = 0ull;

    // prologue: load + store tile 0
    {
        const float* ap = Aptr + (size_t)tid*FEATD;
        #pragma unroll
        for (int q = 0; q < 8; q++) pa[q] = *(const float4*)(ap + q*4);
        const float* bp = Bptr + (size_t)bn_f*FEATD + bq;
        #pragma unroll
        for (int q = 0; q < 4; q++) pb[q] = *(const float4*)(bp + q*4);
    }
    {
        #pragma unroll
        for (int q = 0; q < 8; q++) {
            As[(q*4+0)*GMS + tid] = pa[q].x;
            As[(q*4+1)*GMS + tid] = pa[q].y;
            As[(q*4+2)*GMS + tid] = pa[q].z;
            As[(q*4+3)*GMS + tid] = pa[q].w;
        }
        #pragma unroll
        for (int q = 0; q < 4; q++) {
            float v0 = pb[q].x, v1 = pb[q].y, v2 = pb[q].z, v3 = pb[q].w;
            *(float2*)&Bsd[(bq+q*4+0)*GMS + 2*bn_f] = make_float2(v0, v0);
            *(float2*)&Bsd[(bq+q*4+1)*GMS + 2*bn_f] = make_float2(v1, v1);
            *(float2*)&Bsd[(bq+q*4+2)*GMS + 2*bn_f] = make_float2(v2, v2);
            *(float2*)&Bsd[(bq+q*4+3)*GMS + 2*bn_f] = make_float2(v3, v3);
        }
    }
    __syncthreads();

    for (int kt = 0; kt < NKITER; kt++) {
        int cur = kt & 1;
        if (kt + 1 < NKITER) {
            const float* ap = Aptr + (size_t)(kt+1)*GBK + (size_t)tid*FEATD;
            #pragma unroll
            for (int q = 0; q < 8; q++) pa[q] = *(const float4*)(ap + q*4);
            const float* bp = Bptr + (size_t)(kt+1)*GBK + (size_t)bn_f*FEATD + bq;
            #pragma unroll
            for (int q = 0; q < 4; q++) pb[q] = *(const float4*)(bp + q*4);
        }
        const float* A_ = As  + cur*GBK*GMS;
        const float* B_ = Bsd + cur*GBK*GMS;
        #pragma unroll 8
        for (int kk = 0; kk < GBK; kk++) {
            ulonglong2 a0 = *(const ulonglong2*)(A_ + kk*GMS + tx*4);
            ulonglong2 a1 = *(const ulonglong2*)(A_ + kk*GMS + 64 + tx*4);
            ulonglong2 b0 = *(const ulonglong2*)(B_ + kk*GMS + ty*16);
            ulonglong2 b1 = *(const ulonglong2*)(B_ + kk*GMS + ty*16 + 4);
            ulonglong2 b2 = *(const ulonglong2*)(B_ + kk*GMS + ty*16 + 8);
            ulonglong2 b3 = *(const ulonglong2*)(B_ + kk*GMS + ty*16 + 12);
            fma2(acc[0][0], a0.x, b0.x); fma2(acc[0][1], a0.y, b0.x);
            fma2(acc[0][2], a1.x, b0.x); fma2(acc[0][3], a1.y, b0.x);
            fma2(acc[1][0], a0.x, b0.y); fma2(acc[1][1], a0.y, b0.y);
            fma2(acc[1][2], a1.x, b0.y); fma2(acc[1][3], a1.y, b0.y);
            fma2(acc[2][0], a0.x, b1.x); fma2(acc[2][1], a0.y, b1.x);
            fma2(acc[2][2], a1.x, b1.x); fma2(acc[2][3], a1.y, b1.x);
            fma2(acc[3][0], a0.x, b1.y); fma2(acc[3][1], a0.y, b1.y);
            fma2(acc[3][2], a1.x, b1.y); fma2(acc[3][3], a1.y, b1.y);
            fma2(acc[4][0], a0.x, b2.x); fma2(acc[4][1], a0.y, b2.x);
            fma2(acc[4][2], a1.x, b2.x); fma2(acc[4][3], a1.y, b2.x);
            fma2(acc[5][0], a0.x, b2.y); fma2(acc[5][1], a0.y, b2.y);
            fma2(acc[5][2], a1.x, b2.y); fma2(acc[5][3], a1.y, b2.y);
            fma2(acc[6][0], a0.x, b3.x); fma2(acc[6][1], a0.y, b3.x);
            fma2(acc[6][2], a1.x, b3.x); fma2(acc[6][3], a1.y, b3.x);
            fma2(acc[7][0], a0.x, b3.y); fma2(acc[7][1], a0.y, b3.y);
            fma2(acc[7][2], a1.x, b3.y); fma2(acc[7][3], a1.y, b3.y);
        }
        if (kt + 1 < NKITER) {
            int nxt = cur ^ 1;
            float* A_n = As  + nxt*GBK*GMS;
            float* B_n = Bsd + nxt*GBK*GMS;
            #pragma unroll
            for (int q = 0; q < 8; q++) {
                A_n[(q*4+0)*GMS + tid] = pa[q].x;
                A_n[(q*4+1)*GMS + tid] = pa[q].y;
                A_n[(q*4+2)*GMS + tid] = pa[q].z;
                A_n[(q*4+3)*GMS + tid] = pa[q].w;
            }
            #pragma unroll
            for (int q = 0; q < 4; q++) {
                float v0 = pb[q].x, v1 = pb[q].y, v2 = pb[q].z, v3 = pb[q].w;
                *(float2*)&B_n[(bq+q*4+0)*GMS + 2*bn_f] = make_float2(v0, v0);
                *(float2*)&B_n[(bq+q*4+1)*GMS + 2*bn_f] = make_float2(v1, v1);
                *(float2*)&B_n[(bq+q*4+2)*GMS + 2*bn_f] = make_float2(v2, v2);
                *(float2*)&B_n[(bq+q*4+3)*GMS + 2*bn_f] = make_float2(v3, v3);
            }
            __syncthreads();
        }
    }

    // epilogue: m rows = {m0+tx*4+0..3, m0+64+tx*4+0..3}, n = n0+ty*8+0..7
    float o[8][8];
    #pragma unroll
    for (int j = 0; j < 8; j++) {
        upk2(o[0][j], o[1][j], acc[j][0]);
        upk2(o[2][j], o[3][j], acc[j][1]);
        upk2(o[4][j], o[5][j], acc[j][2]);
        upk2(o[6][j], o[7][j], acc[j][3]);
    }
    float* op = &g_igp[z][0];
    #pragma unroll
    for (int mi = 0; mi < 8; mi++) {
        int m = m0 + (mi < 4 ? tx*4 + mi : 64 + tx*4 + (mi - 4));
        float* dst = &op[(size_t)m*G3 + n0 + ty*8];
        *(float4*)dst       = make_float4(o[mi][0], o[mi][1], o[mi][2], o[mi][3]);
        *(float4*)(dst + 4) = make_float4(o[mi][4], o[mi][5], o[mi][6], o[mi][7]);
    }
}

// ---------------- GRU scan: 32 blocks (one per batch row) ----------------
__global__ void __launch_bounds__(192) k_scan(
    const float* __restrict__ Wh, const float* __restrict__ bi,
    const float* __restrict__ bn, const float* __restrict__ h0,
    float* __restrict__ out_hidden)
{
    extern __shared__ float sWhT[];   // 64*192, WhT[d*192+n]
    __shared__ float sh[64], shg[192], sig[192], sbi[192], sbn[64];
    int b = blockIdx.x, tid = threadIdx.x;
    for (int i = tid; i < 64*G3; i += 192) {
        int d = i / G3, n = i - d*G3;
        sWhT[i] = Wh[n*64 + d];
    }
    sbi[tid] = bi[tid];
    if (tid < 64) { sbn[tid] = bn[tid]; sh[tid] = h0[b*64 + tid]; }
    __syncthreads();

    for (int t = 0; t < SEQ; t++) {
        size_t idx = (size_t)(b*SEQ + t)*G3 + tid;
        float ps = g_igp[0][idx] + g_igp[1][idx] + g_igp[2][idx];
        float acc = 0.f;
        #pragma unroll
        for (int d = 0; d < 64; d++) acc = fmaf(sh[d], sWhT[d*G3 + tid], acc);
        shg[tid] = acc;
        sig[tid] = ps + sbi[tid];
        __syncthreads();
        if (tid < 64) {
            float r  = 1.f / (1.f + expf(-(sig[tid]       + shg[tid])));
            float zz = 1.f / (1.f + expf(-(sig[64 + tid]  + shg[64 + tid])));
            float nn = tanhf(sig[128 + tid] + r * (shg[128 + tid] + sbn[tid]));
            float h  = (1.f - zz) * nn + zz * sh[tid];
            sh[tid] = h;
            g_allh[(size_t)(b*SEQ + t)*64 + tid] = h;
        }
        __syncthreads();
    }
    if (tid < 64) out_hidden[b*64 + tid] = sh[tid];
}

// ---------------- output heads ----------------
__global__ void __launch_bounds__(128) k_head(
    const float* __restrict__ Wa1, const float* __restrict__ ba1,
    const float* __restrict__ Wa2, const float* __restrict__ ba2,
    const float* __restrict__ Wc1, const float* __restrict__ bc1,
    const float* __restrict__ Wc2, const float* __restrict__ bc2,
    float* __restrict__ out_logits, float* __restrict__ out_values)
{
    __shared__ float sh[64], sa[64], sc[64];
    int row = blockIdx.x, tid = threadIdx.x;
    if (tid < 64) sh[tid] = g_allh[(size_t)row*64 + tid];
    __syncthreads();
    if (tid < 64) {
        float a = ba1[tid], c = bc1[tid];
        #pragma unroll
        for (int d = 0; d < 64; d++) {
            float h = sh[d];
            a = fmaf(h, Wa1[d*64 + tid], a);
            c = fmaf(h, Wc1[d*64 + tid], c);
        }
        sa[tid] = tanhf(a);
        sc[tid] = tanhf(c);
    }
    __syncthreads();
    if (tid < 96) {
        float l = ba2[tid];
        #pragma unroll
        for (int j = 0; j < 64; j++) l = fmaf(sa[j], Wa2[j*96 + tid], l);
        out_logits[(size_t)row*96 + tid] = l;
    } else {
        int d = tid - 96;
        float v = sc[d]*Wc2[d] + sc[d+32]*Wc2[d+32];
        #pragma unroll
        for (int o = 16; o > 0; o >>= 1) v += __shfl_xor_sync(0xffffffffu, v, o);
        if (d == 0) out_values[row] = v + bc2[0];
    }
}

// ---------------- launch ----------------
extern "C" void kernel_launch(void* const* d_in, const int* in_sizes, int n_in,
                              void* d_out, int out_size)
{
    const int*   positions       = (const int*)  d_in[0];
    const void*  units_mask      =               d_in[1];
    const int*   tile_type       = (const int*)  d_in[2];
    const int*   relic_positions = (const int*)  d_in[3];
    const void*  relic_mask      =               d_in[4];
    const float* reward          = (const float*)d_in[5];
    const float* hidden          = (const float*)d_in[6];
    const float* emb_tile        = (const float*)d_in[7];
    const float* emb_unit        = (const float*)d_in[8];
    const float* w1 = (const float*)d_in[9];
    const float* b1 = (const float*)d_in[10];
    const float* w2 = (const float*)d_in[11];
    const float* b2 = (const float*)d_in[12];
    const float* w3 = (const float*)d_in[13];
    const float* b3 = (const float*)d_in[14];
    const float* Wi = (const float*)d_in[15];
    const float* Wh = (const float*)d_in[16];
    const float* bi = (const float*)d_in[17];
    const float* bn = (const float*)d_in[18];
    const float* Wa1 = (const float*)d_in[19];
    const float* ba1 = (const float*)d_in[20];
    const float* Wa2 = (const float*)d_in[21];
    const float* ba2 = (const float*)d_in[22];
    const float* Wc1 = (const float*)d_in[23];
    const float* bc1 = (const float*)d_in[24];
    const float* Wc2 = (const float*)d_in[25];
    const float* bc2 = (const float*)d_in[26];

    float* out        = (float*)d_out;
    float* out_logits = out;                       // 4096*96
    float* out_values = out + 393216;              // 4096
    float* out_hidden = out + 393216 + 4096;       // 2048

    const int smem_gc1  = (576*G1STR + 1536) * 4;       // 70656
    const int smem_c2   = (529*C2ISTR + 2048) * 4;      // 50512
    const int smem_c3   = (484*C3ISTR + 8192) * 4;      // 102464
    const int smem_gemm = (4*GBK*GMS) * 4;              // 67584
    const int smem_scan = 64*G3*4;                      // 49152

    cudaFuncSetAttribute(k_grid_conv1, cudaFuncAttributeMaxDynamicSharedMemorySize, smem_gc1);
    cudaFuncSetAttribute(k_conv2,      cudaFuncAttributeMaxDynamicSharedMemorySize, smem_c2);
    cudaFuncSetAttribute(k_conv3,      cudaFuncAttributeMaxDynamicSharedMemorySize, smem_c3);
    cudaFuncSetAttribute(k_gemm,       cudaFuncAttributeMaxDynamicSharedMemorySize, smem_gemm);
    cudaFuncSetAttribute(k_scan,       cudaFuncAttributeMaxDynamicSharedMemorySize, smem_scan);

    k_detect<<<1, 256>>>((const unsigned char*)units_mask, BATCH*SEQ*2*16);
    k_expand<<<(BATCH*SEQ*2*16 + 255)/256, 256>>>(units_mask, relic_mask);

    k_grid_conv1<<<NIMG, 256, smem_gc1>>>(positions, tile_type, relic_positions,
                                          reward, emb_tile, emb_unit, w1, b1);
    k_conv2<<<NIMG, 256, smem_c2>>>(w2, b2);
    k_conv3<<<NIMG, 256, smem_c3>>>(w3, b3);

    dim3 gg(NIMG/GBM, G3/GBN, KSPLIT);
    k_gemm<<<gg, 128, smem_gemm>>>(Wi);

    k_scan<<<BATCH, 192, smem_scan>>>(Wh, bi, bn, hidden, out_hidden);
    k_head<<<NIMG, 128>>>(Wa1, ba1, Wa2, ba2, Wc1, bc1, Wc2, bc2,
                          out_logits, out_values);
}

// round 8
// speedup vs baseline: 1.3202x; 1.0303x over previous
#include <cuda_runtime.h>
#include <math.h>

// ---------------- problem constants ----------------
#define NIMG   4096          // B*S = 32*128
#define BATCH  32
#define SEQ    128
#define MAPW   24
#define G1STR  28            // grid smem channel stride (16B-aligned rows)
#define C1_HO 23
#define C1_IMG (23*23*16)    // 8464
#define C2_HO 22
#define C2_IMG (22*22*32)    // 15488
#define C3_HO 21
#define FEATD (21*21*64)     // 28224
#define G3    192            // 3*RNN_D
#define RNN_D 64

// GEMM tiling
#define GBM 128
#define GBN 64
#define GBK 32
#define GMS 132              // smem row stride (floats)
#define KSPLIT 3
#define KPART (FEATD/KSPLIT)     // 9408
#define NKITER (KPART/GBK)       // 294

// ---------------- packed f32x2 helpers ----------------
typedef unsigned long long u64t;
__device__ __forceinline__ u64t pk2(float lo, float hi) {
    u64t r; asm("mov.b64 %0, {%1,%2};" : "=l"(r) : "f"(lo), "f"(hi)); return r;
}
__device__ __forceinline__ void upk2(float& lo, float& hi, u64t v) {
    asm("mov.b64 {%0,%1}, %2;" : "=f"(lo), "=f"(hi) : "l"(v));
}
__device__ __forceinline__ void fma2(u64t& d, u64t a, u64t b) {
    asm("fma.rn.f32x2 %0, %1, %2, %0;" : "+l"(d) : "l"(a), "l"(b));
}

// ---------------- scratch ----------------
__device__ float g_c1[(size_t)NIMG * C1_IMG];
__device__ float g_c2[(size_t)NIMG * C2_IMG];
__device__ float g_feat[(size_t)NIMG * FEATD];
__device__ float g_igp[KSPLIT][(size_t)NIMG * G3];
__device__ float g_allh[(size_t)NIMG * RNN_D];
__device__ unsigned char g_um8[BATCH*SEQ*2*16];
__device__ unsigned char g_rm8[BATCH*SEQ*6];
__device__ int g_maskkind;   // 0=int32, 1=bool8, 2=float32

// ---------------- mask dtype detection ----------------
__global__ void k_detect(const unsigned char* __restrict__ p, int count) {
    __shared__ int sHi, s80;
    if (threadIdx.x == 0) { sHi = 0; s80 = 0; }
    __syncthreads();
    int hi = 0, b80 = 0;
    for (int i = threadIdx.x; i < count; i += blockDim.x) {
        unsigned char v = p[i];
        if ((i & 3) != 0 && v) hi = 1;
        if ((i & 3) == 2 && v == 0x80) b80 = 1;
    }
    if (hi)  sHi = 1;
    if (b80) s80 = 1;
    __syncthreads();
    if (threadIdx.x == 0) g_maskkind = (!sHi) ? 0 : (s80 ? 2 : 1);
}

__global__ void k_expand(const void* __restrict__ um, const void* __restrict__ rm) {
    int kind = g_maskkind;
    int i = blockIdx.x * blockDim.x + threadIdx.x;
    if (i < BATCH*SEQ*2*16) {
        unsigned char v;
        if (kind == 0)      v = (((const int*)um)[i] != 0);
        else if (kind == 1) v = (((const unsigned char*)um)[i] != 0);
        else                v = (((const float*)um)[i] != 0.f);
        g_um8[i] = v;
    }
    if (i < BATCH*SEQ*6) {
        unsigned char v;
        if (kind == 0)      v = (((const int*)rm)[i] != 0);
        else if (kind == 1) v = (((const unsigned char*)rm)[i] != 0);
        else                v = (((const float*)rm)[i] != 0.f);
        g_rm8[i] = v;
    }
}

// ---------------- generic 2x2-VALID conv block (pixel-register-blocked) ----
// Thread computes PX pixels x 16 output channels (group cg).
// si: input [pixel][ch] with stride ISTR (16B-aligned rows).
// sw: weights [(k*CI+ci)][CO_ALL]. q unrolled x2 for load/FMA overlap.
template<int PX, int NQ, int CO_ALL, int ISTR, int IW, int OW, int NPX>
__device__ __forceinline__ void conv2x2_block(
    const float* __restrict__ si, const float* __restrict__ sw,
    const u64t* bias, float* __restrict__ gout, int cg, int px0, int pxstride)
{
    int pxv[PX]; const float* base[PX];
    #pragma unroll
    for (int p = 0; p < PX; p++) {
        pxv[p] = px0 + p * pxstride;
        int pc = pxv[p] < NPX ? pxv[p] : 0;
        int y = pc / OW, x = pc - y * OW;
        base[p] = si + (y * IW + x) * ISTR;
    }
    u64t acc[PX][8];
    #pragma unroll
    for (int p = 0; p < PX; p++)
        #pragma unroll
        for (int j = 0; j < 8; j++) acc[p][j] = bias[j];

    #pragma unroll 1
    for (int k = 0; k < 4; k++) {
        const int off = ((k >> 1) * IW + (k & 1)) * ISTR;
        #pragma unroll 2
        for (int q = 0; q < NQ; q++) {
            float4 in[PX];
            #pragma unroll
            for (int p = 0; p < PX; p++)
                in[p] = *(const float4*)(base[p] + off + q * 4);
            const float* wbase = &sw[(k * NQ * 4 + q * 4) * CO_ALL + cg * 16];
            #pragma unroll
            for (int cc = 0; cc < 4; cc++) {
                const ulonglong2* wp = (const ulonglong2*)(wbase + cc * CO_ALL);
                ulonglong2 w0 = wp[0], w1 = wp[1], w2 = wp[2], w3 = wp[3];
                #pragma unroll
                for (int p = 0; p < PX; p++) {
                    float v = cc == 0 ? in[p].x : cc == 1 ? in[p].y
                            : cc == 2 ? in[p].z : in[p].w;
                    u64t vd = pk2(v, v);
                    fma2(acc[p][0], vd, w0.x); fma2(acc[p][1], vd, w0.y);
                    fma2(acc[p][2], vd, w1.x); fma2(acc[p][3], vd, w1.y);
                    fma2(acc[p][4], vd, w2.x); fma2(acc[p][5], vd, w2.y);
                    fma2(acc[p][6], vd, w3.x); fma2(acc[p][7], vd, w3.y);
                }
            }
        }
    }
    #pragma unroll
    for (int p = 0; p < PX; p++) {
        if (pxv[p] < NPX) {
            float4* op = (float4*)&gout[(size_t)pxv[p] * CO_ALL + cg * 16];
            #pragma unroll
            for (int g = 0; g < 4; g++) {
                float a0, a1, a2, a3;
                upk2(a0, a1, acc[p][2*g]); upk2(a2, a3, acc[p][2*g+1]);
                float4 v;
                v.x = fmaxf(a0, 0.f); v.y = fmaxf(a1, 0.f);
                v.z = fmaxf(a2, 0.f); v.w = fmaxf(a3, 0.f);
                op[g] = v;
            }
        }
    }
}

// ---------------- fused grid build + conv1 (24ch->16ch) ----------------
__global__ void __launch_bounds__(256) k_grid_conv1(
    const int* __restrict__ positions, const int* __restrict__ tile_type,
    const int* __restrict__ relic_positions, const float* __restrict__ reward,
    const float* __restrict__ emb_tile, const float* __restrict__ emb_unit,
    const float* __restrict__ w1, const float* __restrict__ b1)
{
    extern __shared__ float sm[];
    float* sg = sm;                  // 576*28 = 16128 floats
    float* sw = sm + 576*G1STR;      // 1536 floats (64512B offset, aligned)
    __shared__ int   spos[2][16][2];
    __shared__ unsigned char sum_[2][16];
    __shared__ int   srpos[6][2];
    __shared__ unsigned char srm[6];
    __shared__ float semb_u[128];
    __shared__ float semb_t[12];

    int img = blockIdx.x;
    int tid = threadIdx.x;

    if (tid < 64)  ((int*)spos)[tid] = positions[(size_t)img*64 + tid];
    if (tid < 32)  ((unsigned char*)sum_)[tid] = g_um8[img*32 + tid];
    if (tid < 12)  ((int*)srpos)[tid] = relic_positions[(size_t)img*12 + tid];
    if (tid < 6)   srm[tid] = g_rm8[img*6 + tid];
    if (tid < 12)  semb_t[tid] = emb_tile[tid];
    if (tid < 128) semb_u[tid] = emb_unit[tid];
    for (int i = tid; i < 1536; i += 256) sw[i] = w1[i];
    float rw = reward[img];
    u64t bias[8];
    #pragma unroll
    for (int j = 0; j < 8; j++) bias[j] = pk2(b1[2*j], b1[2*j+1]);
    __syncthreads();

    // build grid (24 channels, padded stride 28)
    for (int p = tid; p < 576; p += 256) {
        int y = p / MAPW, x = p - y * MAPW;
        float e[16];
        #pragma unroll
        for (int j = 0; j < 16; j++) e[j] = 0.f;
        float cnt0 = 0.f, cnt1 = 0.f;
        #pragma unroll
        for (int t = 0; t < 2; t++) {
            #pragma unroll
            for (int u = 0; u < 16; u++) {
                if (sum_[t][u] && spos[t][u][0] == y && spos[t][u][1] == x) {
                    if (t == 0) cnt0 += 1.f; else cnt1 += 1.f;
                    #pragma unroll
                    for (int j = 0; j < 8; j++) e[t*8 + j] += semb_u[u*8 + j];
                }
            }
        }
        float rc = 0.f;
        #pragma unroll
        for (int r = 0; r < 6; r++)
            if (srm[r] && srpos[r][0] == y && srpos[r][1] == x) rc += 1.f;
        int tt = tile_type[(size_t)img*576 + p];
        float* gp = &sg[p * G1STR];
        gp[0] = semb_t[tt*4+0]; gp[1] = semb_t[tt*4+1];
        gp[2] = semb_t[tt*4+2]; gp[3] = semb_t[tt*4+3];
        gp[4] = cnt0 * 0.0625f; gp[5] = cnt1 * 0.0625f;
        #pragma unroll
        for (int j = 0; j < 16; j++) gp[6 + j] = e[j];
        gp[22] = rc; gp[23] = rw;
    }
    __syncthreads();

    // conv1: PX=3 pixels per thread, all 16 out channels
    conv2x2_block<3, 6, 16, G1STR, 24, 23, 529>(
        sg, sw, bias, g_c1 + (size_t)img*C1_IMG, 0, tid, 256);
}

// ---------------- conv2: 16ch 23x23 -> 32ch 22x22 ----------------
#define C2ISTR 20
__global__ void __launch_bounds__(256) k_conv2(const float* __restrict__ w2,
                                               const float* __restrict__ b2)
{
    extern __shared__ float sm[];
    float* si = sm;                // 529*20 = 10580 floats
    float* sw = sm + 529*C2ISTR;   // 2048 floats (42320B offset, aligned)
    int img = blockIdx.x, tid = threadIdx.x;
    const float4* in4 = (const float4*)&g_c1[(size_t)img*C1_IMG];
    for (int i4 = tid; i4 < 529*4; i4 += 256) {
        int px = i4 >> 2, c4 = i4 & 3;
        *(float4*)&si[px*C2ISTR + c4*4] = in4[i4];
    }
    for (int i = tid; i < 2048; i += 256) sw[i] = w2[i];
    int cg = tid >> 7, ps = tid & 127;
    u64t bias[8];
    #pragma unroll
    for (int j = 0; j < 8; j++) bias[j] = pk2(b2[cg*16 + 2*j], b2[cg*16 + 2*j + 1]);
    __syncthreads();

    conv2x2_block<4, 4, 32, C2ISTR, 23, 22, 484>(
        si, sw, bias, g_c2 + (size_t)img*C2_IMG, cg, ps, 128);
}

// ---------------- conv3: 32ch 22x22 -> 64ch 21x21 ----------------
#define C3ISTR 36
__global__ void __launch_bounds__(256) k_conv3(const float* __restrict__ w3,
                                               const float* __restrict__ b3)
{
    extern __shared__ float sm[];
    float* si = sm;                // 484*36 = 17424 floats
    float* sw = sm + 484*C3ISTR;   // 8192 floats (69696B offset, aligned)
    int img = blockIdx.x, tid = threadIdx.x;
    const float4* in4 = (const float4*)&g_c2[(size_t)img*C2_IMG];
    for (int i4 = tid; i4 < 484*8; i4 += 256) {
        int px = i4 >> 3, c4 = i4 & 7;
        *(float4*)&si[px*C3ISTR + c4*4] = in4[i4];
    }
    for (int i = tid; i < 8192; i += 256) sw[i] = w3[i];
    int cg = tid >> 6, ps = tid & 63;
    u64t bias[8];
    #pragma unroll
    for (int j = 0; j < 8; j++) bias[j] = pk2(b3[cg*16 + 2*j], b3[cg*16 + 2*j + 1]);
    __syncthreads();

    float* out = g_feat + (size_t)img*FEATD;
    conv2x2_block<4, 8, 64, C3ISTR, 22, 21, 441>(si, sw, bias, out, cg, ps, 64);
    conv2x2_block<3, 8, 64, C3ISTR, 22, 21, 441>(si, sw, bias, out, cg, 256 + ps, 64);
}

// ---------------- big GEMM: IG = feat @ Wi^T (split-K=3 partials) ---------
// 128 threads, tile 128m x 64n x 32k; thread block 8m x 8n (FFMA2).
// A natural [k][m]; B duplicated (b,b) pairs [k][2n] -> warp-broadcast reads.
__global__ void __launch_bounds__(128, 3) k_gemm(const float* __restrict__ Wi)
{
    extern __shared__ float sm[];
    float* As  = sm;                  // 2 * 32 * 132
    float* Bsd = sm + 2*GBK*GMS;      // 2 * 32 * 132 (33792B offset, aligned)
    int tid = threadIdx.x;
    int m0 = blockIdx.x * GBM, n0 = blockIdx.y * GBN, z = blockIdx.z;
    const float* Aptr = g_feat + (size_t)m0*FEATD + (size_t)z*KPART;
    const float* Bptr = Wi     + (size_t)n0*FEATD + (size_t)z*KPART;

    int tx = tid & 15, ty = tid >> 4;          // compute map (16 x 8)
    int bn_f = tid & 63, bq = (tid >> 6) * 16; // B fill: k base

    float4 pa[8], pb[4];
    u64t acc[8][4];                            // [n][m-chunk]
    #pragma unroll
    for (int j = 0; j < 8; j++)
        #pragma unroll
        for (int c = 0; c < 4; c++) acc[j][c] = 0ull;

    // prologue: load + store tile 0
    {
        const float* ap = Aptr + (size_t)tid*FEATD;
        #pragma unroll
        for (int q = 0; q < 8; q++) pa[q] = *(const float4*)(ap + q*4);
        const float* bp = Bptr + (size_t)bn_f*FEATD + bq;
        #pragma unroll
        for (int q = 0; q < 4; q++) pb[q] = *(const float4*)(bp + q*4);
    }
    {
        #pragma unroll
        for (int q = 0; q < 8; q++) {
            As[(q*4+0)*GMS + tid] = pa[q].x;
            As[(q*4+1)*GMS + tid] = pa[q].y;
            As[(q*4+2)*GMS + tid] = pa[q].z;
            As[(q*4+3)*GMS + tid] = pa[q].w;
        }
        #pragma unroll
        for (int q = 0; q < 4; q++) {
            float v0 = pb[q].x, v1 = pb[q].y, v2 = pb[q].z, v3 = pb[q].w;
            *(float2*)&Bsd[(bq+q*4+0)*GMS + 2*bn_f] = make_float2(v0, v0);
            *(float2*)&Bsd[(bq+q*4+1)*GMS + 2*bn_f] = make_float2(v1, v1);
            *(float2*)&Bsd[(bq+q*4+2)*GMS + 2*bn_f] = make_float2(v2, v2);
            *(float2*)&Bsd[(bq+q*4+3)*GMS + 2*bn_f] = make_float2(v3, v3);
        }
    }
    __syncthreads();

    for (int kt = 0; kt < NKITER; kt++) {
        int cur = kt & 1;
        if (kt + 1 < NKITER) {
            const float* ap = Aptr + (size_t)(kt+1)*GBK + (size_t)tid*FEATD;
            #pragma unroll
            for (int q = 0; q < 8; q++) pa[q] = *(const float4*)(ap + q*4);
            const float* bp = Bptr + (size_t)(kt+1)*GBK + (size_t)bn_f*FEATD + bq;
            #pragma unroll
            for (int q = 0; q < 4; q++) pb[q] = *(const float4*)(bp + q*4);
        }
        const float* A_ = As  + cur*GBK*GMS;
        const float* B_ = Bsd + cur*GBK*GMS;
        #pragma unroll 16
        for (int kk = 0; kk < GBK; kk++) {
            ulonglong2 a0 = *(const ulonglong2*)(A_ + kk*GMS + tx*4);
            ulonglong2 a1 = *(const ulonglong2*)(A_ + kk*GMS + 64 + tx*4);
            ulonglong2 b0 = *(const ulonglong2*)(B_ + kk*GMS + ty*16);
            ulonglong2 b1 = *(const ulonglong2*)(B_ + kk*GMS + ty*16 + 4);
            ulonglong2 b2 = *(const ulonglong2*)(B_ + kk*GMS + ty*16 + 8);
            ulonglong2 b3 = *(const ulonglong2*)(B_ + kk*GMS + ty*16 + 12);
            fma2(acc[0][0], a0.x, b0.x); fma2(acc[0][1], a0.y, b0.x);
            fma2(acc[0][2], a1.x, b0.x); fma2(acc[0][3], a1.y, b0.x);
            fma2(acc[1][0], a0.x, b0.y); fma2(acc[1][1], a0.y, b0.y);
            fma2(acc[1][2], a1.x, b0.y); fma2(acc[1][3], a1.y, b0.y);
            fma2(acc[2][0], a0.x, b1.x); fma2(acc[2][1], a0.y, b1.x);
            fma2(acc[2][2], a1.x, b1.x); fma2(acc[2][3], a1.y, b1.x);
            fma2(acc[3][0], a0.x, b1.y); fma2(acc[3][1], a0.y, b1.y);
            fma2(acc[3][2], a1.x, b1.y); fma2(acc[3][3], a1.y, b1.y);
            fma2(acc[4][0], a0.x, b2.x); fma2(acc[4][1], a0.y, b2.x);
            fma2(acc[4][2], a1.x, b2.x); fma2(acc[4][3], a1.y, b2.x);
            fma2(acc[5][0], a0.x, b2.y); fma2(acc[5][1], a0.y, b2.y);
            fma2(acc[5][2], a1.x, b2.y); fma2(acc[5][3], a1.y, b2.y);
            fma2(acc[6][0], a0.x, b3.x); fma2(acc[6][1], a0.y, b3.x);
            fma2(acc[6][2], a1.x, b3.x); fma2(acc[6][3], a1.y, b3.x);
            fma2(acc[7][0], a0.x, b3.y); fma2(acc[7][1], a0.y, b3.y);
            fma2(acc[7][2], a1.x, b3.y); fma2(acc[7][3], a1.y, b3.y);
        }
        if (kt + 1 < NKITER) {
            int nxt = cur ^ 1;
            float* A_n = As  + nxt*GBK*GMS;
            float* B_n = Bsd + nxt*GBK*GMS;
            #pragma unroll
            for (int q = 0; q < 8; q++) {
                A_n[(q*4+0)*GMS + tid] = pa[q].x;
                A_n[(q*4+1)*GMS + tid] = pa[q].y;
                A_n[(q*4+2)*GMS + tid] = pa[q].z;
                A_n[(q*4+3)*GMS + tid] = pa[q].w;
            }
            #pragma unroll
            for (int q = 0; q < 4; q++) {
                float v0 = pb[q].x, v1 = pb[q].y, v2 = pb[q].z, v3 = pb[q].w;
                *(float2*)&B_n[(bq+q*4+0)*GMS + 2*bn_f] = make_float2(v0, v0);
                *(float2*)&B_n[(bq+q*4+1)*GMS + 2*bn_f] = make_float2(v1, v1);
                *(float2*)&B_n[(bq+q*4+2)*GMS + 2*bn_f] = make_float2(v2, v2);
                *(float2*)&B_n[(bq+q*4+3)*GMS + 2*bn_f] = make_float2(v3, v3);
            }
            __syncthreads();
        }
    }

    // epilogue: m rows = {m0+tx*4+0..3, m0+64+tx*4+0..3}, n = n0+ty*8+0..7
    float o[8][8];
    #pragma unroll
    for (int j = 0; j < 8; j++) {
        upk2(o[0][j], o[1][j], acc[j][0]);
        upk2(o[2][j], o[3][j], acc[j][1]);
        upk2(o[4][j], o[5][j], acc[j][2]);
        upk2(o[6][j], o[7][j], acc[j][3]);
    }
    float* op = &g_igp[z][0];
    #pragma unroll
    for (int mi = 0; mi < 8; mi++) {
        int m = m0 + (mi < 4 ? tx*4 + mi : 64 + tx*4 + (mi - 4));
        float* dst = &op[(size_t)m*G3 + n0 + ty*8];
        *(float4*)dst       = make_float4(o[mi][0], o[mi][1], o[mi][2], o[mi][3]);
        *(float4*)(dst + 4) = make_float4(o[mi][4], o[mi][5], o[mi][6], o[mi][7]);
    }
}

// ---------------- GRU scan: 32 blocks (one per batch row) ----------------
__global__ void __launch_bounds__(192) k_scan(
    const float* __restrict__ Wh, const float* __restrict__ bi,
    const float* __restrict__ bn, const float* __restrict__ h0,
    float* __restrict__ out_hidden)
{
    extern __shared__ float sWhT[];   // 64*192, WhT[d*192+n]
    __shared__ float sh[64], shg[192], sig[192], sbi[192], sbn[64];
    int b = blockIdx.x, tid = threadIdx.x;
    for (int i = tid; i < 64*G3; i += 192) {
        int d = i / G3, n = i - d*G3;
        sWhT[i] = Wh[n*64 + d];
    }
    sbi[tid] = bi[tid];
    if (tid < 64) { sbn[tid] = bn[tid]; sh[tid] = h0[b*64 + tid]; }
    __syncthreads();

    for (int t = 0; t < SEQ; t++) {
        size_t idx = (size_t)(b*SEQ + t)*G3 + tid;
        float ps = g_igp[0][idx] + g_igp[1][idx] + g_igp[2][idx];
        float acc = 0.f;
        #pragma unroll
        for (int d = 0; d < 64; d++) acc = fmaf(sh[d], sWhT[d*G3 + tid], acc);
        shg[tid] = acc;
        sig[tid] = ps + sbi[tid];
        __syncthreads();
        if (tid < 64) {
            float r  = 1.f / (1.f + expf(-(sig[tid]       + shg[tid])));
            float zz = 1.f / (1.f + expf(-(sig[64 + tid]  + shg[64 + tid])));
            float nn = tanhf(sig[128 + tid] + r * (shg[128 + tid] + sbn[tid]));
            float h  = (1.f - zz) * nn + zz * sh[tid];
            sh[tid] = h;
            g_allh[(size_t)(b*SEQ + t)*64 + tid] = h;
        }
        __syncthreads();
    }
    if (tid < 64) out_hidden[b*64 + tid] = sh[tid];
}

// ---------------- output heads ----------------
__global__ void __launch_bounds__(128) k_head(
    const float* __restrict__ Wa1, const float* __restrict__ ba1,
    const float* __restrict__ Wa2, const float* __restrict__ ba2,
    const float* __restrict__ Wc1, const float* __restrict__ bc1,
    const float* __restrict__ Wc2, const float* __restrict__ bc2,
    float* __restrict__ out_logits, float* __restrict__ out_values)
{
    __shared__ float sh[64], sa[64], sc[64];
    int row = blockIdx.x, tid = threadIdx.x;
    if (tid < 64) sh[tid] = g_allh[(size_t)row*64 + tid];
    __syncthreads();
    if (tid < 64) {
        float a = ba1[tid], c = bc1[tid];
        #pragma unroll
        for (int d = 0; d < 64; d++) {
            float h = sh[d];
            a = fmaf(h, Wa1[d*64 + tid], a);
            c = fmaf(h, Wc1[d*64 + tid], c);
        }
        sa[tid] = tanhf(a);
        sc[tid] = tanhf(c);
    }
    __syncthreads();
    if (tid < 96) {
        float l = ba2[tid];
        #pragma unroll
        for (int j = 0; j < 64; j++) l = fmaf(sa[j], Wa2[j*96 + tid], l);
        out_logits[(size_t)row*96 + tid] = l;
    } else {
        int d = tid - 96;
        float v = sc[d]*Wc2[d] + sc[d+32]*Wc2[d+32];
        #pragma unroll
        for (int o = 16; o > 0; o >>= 1) v += __shfl_xor_sync(0xffffffffu, v, o);
        if (d == 0) out_values[row] = v + bc2[0];
    }
}

// ---------------- launch ----------------
extern "C" void kernel_launch(void* const* d_in, const int* in_sizes, int n_in,
                              void* d_out, int out_size)
{
    const int*   positions       = (const int*)  d_in[0];
    const void*  units_mask      =               d_in[1];
    const int*   tile_type       = (const int*)  d_in[2];
    const int*   relic_positions = (const int*)  d_in[3];
    const void*  relic_mask      =               d_in[4];
    const float* reward          = (const float*)d_in[5];
    const float* hidden          = (const float*)d_in[6];
    const float* emb_tile        = (const float*)d_in[7];
    const float* emb_unit        = (const float*)d_in[8];
    const float* w1 = (const float*)d_in[9];
    const float* b1 = (const float*)d_in[10];
    const float* w2 = (const float*)d_in[11];
    const float* b2 = (const float*)d_in[12];
    const float* w3 = (const float*)d_in[13];
    const float* b3 = (const float*)d_in[14];
    const float* Wi = (const float*)d_in[15];
    const float* Wh = (const float*)d_in[16];
    const float* bi = (const float*)d_in[17];
    const float* bn = (const float*)d_in[18];
    const float* Wa1 = (const float*)d_in[19];
    const float* ba1 = (const float*)d_in[20];
    const float* Wa2 = (const float*)d_in[21];
    const float* ba2 = (const float*)d_in[22];
    const float* Wc1 = (const float*)d_in[23];
    const float* bc1 = (const float*)d_in[24];
    const float* Wc2 = (const float*)d_in[25];
    const float* bc2 = (const float*)d_in[26];

    float* out        = (float*)d_out;
    float* out_logits = out;                       // 4096*96
    float* out_values = out + 393216;              // 4096
    float* out_hidden = out + 393216 + 4096;       // 2048

    const int smem_gc1  = (576*G1STR + 1536) * 4;       // 70656
    const int smem_c2   = (529*C2ISTR + 2048) * 4;      // 50512
    const int smem_c3   = (484*C3ISTR + 8192) * 4;      // 102464
    const int smem_gemm = (4*GBK*GMS) * 4;              // 67584
    const int smem_scan = 64*G3*4;                      // 49152

    cudaFuncSetAttribute(k_grid_conv1, cudaFuncAttributeMaxDynamicSharedMemorySize, smem_gc1);
    cudaFuncSetAttribute(k_conv2,      cudaFuncAttributeMaxDynamicSharedMemorySize, smem_c2);
    cudaFuncSetAttribute(k_conv3,      cudaFuncAttributeMaxDynamicSharedMemorySize, smem_c3);
    cudaFuncSetAttribute(k_gemm,       cudaFuncAttributeMaxDynamicSharedMemorySize, smem_gemm);
    cudaFuncSetAttribute(k_scan,       cudaFuncAttributeMaxDynamicSharedMemorySize, smem_scan);

    k_detect<<<1, 256>>>((const unsigned char*)units_mask, BATCH*SEQ*2*16);
    k_expand<<<(BATCH*SEQ*2*16 + 255)/256, 256>>>(units_mask, relic_mask);

    k_grid_conv1<<<NIMG, 256, smem_gc1>>>(positions, tile_type, relic_positions,
                                          reward, emb_tile, emb_unit, w1, b1);
    k_conv2<<<NIMG, 256, smem_c2>>>(w2, b2);
    k_conv3<<<NIMG, 256, smem_c3>>>(w3, b3);

    dim3 gg(NIMG/GBM, G3/GBN, KSPLIT);
    k_gemm<<<gg, 128, smem_gemm>>>(Wi);

    k_scan<<<BATCH, 192, smem_scan>>>(Wh, bi, bn, hidden, out_hidden);
    k_head<<<NIMG, 128>>>(Wa1, ba1, Wa2, ba2, Wc1, bc1, Wc2, bc2,
                          out_logits, out_values);
}

// round 10
// speedup vs baseline: 1.3584x; 1.0289x over previous
#include <cuda_runtime.h>
#include <math.h>

// ---------------- problem constants ----------------
#define NIMG   4096          // B*S = 32*128
#define BATCH  32
#define SEQ    128
#define MAPW   24
#define G1STR  28            // grid smem channel stride (16B-aligned rows)
#define C1_HO 23
#define C1_IMG (23*23*16)    // 8464
#define C2_HO 22
#define C2_IMG (22*22*32)    // 15488
#define C3_HO 21
#define FEATD (21*21*64)     // 28224
#define G3    192            // 3*RNN_D
#define RNN_D 64

// GEMM tiling
#define GBM 128
#define GBN 64
#define GBK 32
#define GMS 132              // smem row stride (floats)
#define KSPLIT 3
#define KPART (FEATD/KSPLIT)     // 9408
#define NKITER (KPART/GBK)       // 294

// ---------------- packed f32x2 helpers ----------------
typedef unsigned long long u64t;
__device__ __forceinline__ u64t pk2(float lo, float hi) {
    u64t r; asm("mov.b64 %0, {%1,%2};" : "=l"(r) : "f"(lo), "f"(hi)); return r;
}
__device__ __forceinline__ void upk2(float& lo, float& hi, u64t v) {
    asm("mov.b64 {%0,%1}, %2;" : "=f"(lo), "=f"(hi) : "l"(v));
}
__device__ __forceinline__ void fma2(u64t& d, u64t a, u64t b) {
    asm("fma.rn.f32x2 %0, %1, %2, %0;" : "+l"(d) : "l"(a), "l"(b));
}

// ---------------- scratch ----------------
__device__ float g_c1[(size_t)NIMG * C1_IMG];
__device__ float g_c2[(size_t)NIMG * C2_IMG];
__device__ float g_feat[(size_t)NIMG * FEATD];
__device__ float g_igp[KSPLIT][(size_t)NIMG * G3];
__device__ float g_allh[(size_t)NIMG * RNN_D];
__device__ unsigned char g_um8[BATCH*SEQ*2*16];
__device__ unsigned char g_rm8[BATCH*SEQ*6];
__device__ int g_maskkind;   // 0=int32, 1=bool8, 2=float32

// ---------------- fused mask dtype detection + expansion (1 block) -------
__global__ void k_masks(const void* __restrict__ um, const void* __restrict__ rm)
{
    __shared__ int sHi, s80, skind;
    int tid = threadIdx.x;
    if (tid == 0) { sHi = 0; s80 = 0; }
    __syncthreads();
    const unsigned char* p = (const unsigned char*)um;
    int hi = 0, b80 = 0;
    for (int i = tid; i < BATCH*SEQ*2*16; i += 256) {
        unsigned char v = p[i];
        if ((i & 3) != 0 && v) hi = 1;
        if ((i & 3) == 2 && v == 0x80) b80 = 1;
    }
    if (hi)  sHi = 1;
    if (b80) s80 = 1;
    __syncthreads();
    if (tid == 0) {
        skind = (!sHi) ? 0 : (s80 ? 2 : 1);
        g_maskkind = skind;
    }
    __syncthreads();
    int kind = skind;
    for (int i = tid; i < BATCH*SEQ*2*16; i += 256) {
        unsigned char v;
        if (kind == 0)      v = (((const int*)um)[i] != 0);
        else if (kind == 1) v = (((const unsigned char*)um)[i] != 0);
        else                v = (((const float*)um)[i] != 0.f);
        g_um8[i] = v;
    }
    for (int i = tid; i < BATCH*SEQ*6; i += 256) {
        unsigned char v;
        if (kind == 0)      v = (((const int*)rm)[i] != 0);
        else if (kind == 1) v = (((const unsigned char*)rm)[i] != 0);
        else                v = (((const float*)rm)[i] != 0.f);
        g_rm8[i] = v;
    }
}

// ---------------- generic 2x2-VALID conv block (pixel-register-blocked) ----
template<int PX, int NQ, int CO_ALL, int ISTR, int IW, int OW, int NPX>
__device__ __forceinline__ void conv2x2_block(
    const float* __restrict__ si, const float* __restrict__ sw,
    const u64t* bias, float* __restrict__ gout, int cg, int px0, int pxstride)
{
    int pxv[PX]; const float* base[PX];
    #pragma unroll
    for (int p = 0; p < PX; p++) {
        pxv[p] = px0 + p * pxstride;
        int pc = pxv[p] < NPX ? pxv[p] : 0;
        int y = pc / OW, x = pc - y * OW;
        base[p] = si + (y * IW + x) * ISTR;
    }
    u64t acc[PX][8];
    #pragma unroll
    for (int p = 0; p < PX; p++)
        #pragma unroll
        for (int j = 0; j < 8; j++) acc[p][j] = bias[j];

    #pragma unroll 1
    for (int k = 0; k < 4; k++) {
        const int off = ((k >> 1) * IW + (k & 1)) * ISTR;
        #pragma unroll 2
        for (int q = 0; q < NQ; q++) {
            float4 in[PX];
            #pragma unroll
            for (int p = 0; p < PX; p++)
                in[p] = *(const float4*)(base[p] + off + q * 4);
            const float* wbase = &sw[(k * NQ * 4 + q * 4) * CO_ALL + cg * 16];
            #pragma unroll
            for (int cc = 0; cc < 4; cc++) {
                const ulonglong2* wp = (const ulonglong2*)(wbase + cc * CO_ALL);
                ulonglong2 w0 = wp[0], w1 = wp[1], w2 = wp[2], w3 = wp[3];
                #pragma unroll
                for (int p = 0; p < PX; p++) {
                    float v = cc == 0 ? in[p].x : cc == 1 ? in[p].y
                            : cc == 2 ? in[p].z : in[p].w;
                    u64t vd = pk2(v, v);
                    fma2(acc[p][0], vd, w0.x); fma2(acc[p][1], vd, w0.y);
                    fma2(acc[p][2], vd, w1.x); fma2(acc[p][3], vd, w1.y);
                    fma2(acc[p][4], vd, w2.x); fma2(acc[p][5], vd, w2.y);
                    fma2(acc[p][6], vd, w3.x); fma2(acc[p][7], vd, w3.y);
                }
            }
        }
    }
    #pragma unroll
    for (int p = 0; p < PX; p++) {
        if (pxv[p] < NPX) {
            float4* op = (float4*)&gout[(size_t)pxv[p] * CO_ALL + cg * 16];
            #pragma unroll
            for (int g = 0; g < 4; g++) {
                float a0, a1, a2, a3;
                upk2(a0, a1, acc[p][2*g]); upk2(a2, a3, acc[p][2*g+1]);
                float4 v;
                v.x = fmaxf(a0, 0.f); v.y = fmaxf(a1, 0.f);
                v.z = fmaxf(a2, 0.f); v.w = fmaxf(a3, 0.f);
                op[g] = v;
            }
        }
    }
}

// ---------------- fused grid build + conv1 (24ch->16ch) ----------------
__global__ void __launch_bounds__(256) k_grid_conv1(
    const int* __restrict__ positions, const int* __restrict__ tile_type,
    const int* __restrict__ relic_positions, const float* __restrict__ reward,
    const float* __restrict__ emb_tile, const float* __restrict__ emb_unit,
    const float* __restrict__ w1, const float* __restrict__ b1)
{
    extern __shared__ float sm[];
    float* sg = sm;                  // 576*28 = 16128 floats
    float* sw = sm + 576*G1STR;      // 1536 floats (64512B offset, aligned)
    __shared__ int   spos[2][16][2];
    __shared__ unsigned char sum_[2][16];
    __shared__ int   srpos[6][2];
    __shared__ unsigned char srm[6];
    __shared__ float semb_u[128];
    __shared__ float semb_t[12];

    int img = blockIdx.x;
    int tid = threadIdx.x;

    if (tid < 64)  ((int*)spos)[tid] = positions[(size_t)img*64 + tid];
    if (tid < 32)  ((unsigned char*)sum_)[tid] = g_um8[img*32 + tid];
    if (tid < 12)  ((int*)srpos)[tid] = relic_positions[(size_t)img*12 + tid];
    if (tid < 6)   srm[tid] = g_rm8[img*6 + tid];
    if (tid < 12)  semb_t[tid] = emb_tile[tid];
    if (tid < 128) semb_u[tid] = emb_unit[tid];
    for (int i = tid; i < 1536; i += 256) sw[i] = w1[i];
    float rw = reward[img];
    u64t bias[8];
    #pragma unroll
    for (int j = 0; j < 8; j++) bias[j] = pk2(b1[2*j], b1[2*j+1]);
    __syncthreads();

    // build grid (24 channels, padded stride 28)
    for (int p = tid; p < 576; p += 256) {
        int y = p / MAPW, x = p - y * MAPW;
        float e[16];
        #pragma unroll
        for (int j = 0; j < 16; j++) e[j] = 0.f;
        float cnt0 = 0.f, cnt1 = 0.f;
        #pragma unroll
        for (int t = 0; t < 2; t++) {
            #pragma unroll
            for (int u = 0; u < 16; u++) {
                if (sum_[t][u] && spos[t][u][0] == y && spos[t][u][1] == x) {
                    if (t == 0) cnt0 += 1.f; else cnt1 += 1.f;
                    #pragma unroll
                    for (int j = 0; j < 8; j++) e[t*8 + j] += semb_u[u*8 + j];
                }
            }
        }
        float rc = 0.f;
        #pragma unroll
        for (int r = 0; r < 6; r++)
            if (srm[r] && srpos[r][0] == y && srpos[r][1] == x) rc += 1.f;
        int tt = tile_type[(size_t)img*576 + p];
        float* gp = &sg[p * G1STR];
        gp[0] = semb_t[tt*4+0]; gp[1] = semb_t[tt*4+1];
        gp[2] = semb_t[tt*4+2]; gp[3] = semb_t[tt*4+3];
        gp[4] = cnt0 * 0.0625f; gp[5] = cnt1 * 0.0625f;
        #pragma unroll
        for (int j = 0; j < 16; j++) gp[6 + j] = e[j];
        gp[22] = rc; gp[23] = rw;
    }
    __syncthreads();

    // conv1: PX=3 pixels per thread, all 16 out channels
    conv2x2_block<3, 6, 16, G1STR, 24, 23, 529>(
        sg, sw, bias, g_c1 + (size_t)img*C1_IMG, 0, tid, 256);
}

// ---------------- conv2: 16ch 23x23 -> 32ch 22x22, dup-pair inputs --------
#define C2ISTR 36   // 16 ch duplicated = 32 floats + pad to 36 (144B rows)
__global__ void __launch_bounds__(256, 2) k_conv2(const float* __restrict__ w2,
                                                  const float* __restrict__ b2)
{
    extern __shared__ float sm[];
    float* si = sm;                 // 529*36 = 19044 floats (dup pairs)
    float* sw = sm + 529*C2ISTR;    // 2048 floats (76176B offset, 16B aligned)
    int img = blockIdx.x, tid = threadIdx.x;
    const float4* in4 = (const float4*)&g_c1[(size_t)img*C1_IMG];
    for (int i4 = tid; i4 < 529*4; i4 += 256) {
        int px = i4 >> 2, c4 = i4 & 3;
        float4 v = in4[i4];
        ulonglong2 d0, d1;
        d0.x = pk2(v.x, v.x); d0.y = pk2(v.y, v.y);
        d1.x = pk2(v.z, v.z); d1.y = pk2(v.w, v.w);
        *(ulonglong2*)&si[px*C2ISTR + c4*8]     = d0;
        *(ulonglong2*)&si[px*C2ISTR + c4*8 + 4] = d1;
    }
    for (int i = tid; i < 2048; i += 256) sw[i] = w2[i];
    int cg = tid >> 7, ps = tid & 127;
    u64t bias[8];
    #pragma unroll
    for (int j = 0; j < 8; j++) bias[j] = pk2(b2[cg*16 + 2*j], b2[cg*16 + 2*j + 1]);
    __syncthreads();

    // 4 pixels per thread: ps, ps+128, ps+256, ps+384 (guard 484)
    int pxv[4]; const float* base[4];
    #pragma unroll
    for (int p = 0; p < 4; p++) {
        pxv[p] = ps + p * 128;
        int pc = pxv[p] < 484 ? pxv[p] : 0;
        int y = pc / 22, x = pc - y * 22;
        base[p] = si + (y * 23 + x) * C2ISTR;
    }
    u64t acc[4][8];
    #pragma unroll
    for (int p = 0; p < 4; p++)
        #pragma unroll
        for (int j = 0; j < 8; j++) acc[p][j] = bias[j];

    #pragma unroll 1
    for (int k = 0; k < 4; k++) {
        const int off = ((k >> 1) * 23 + (k & 1)) * C2ISTR;
        #pragma unroll 2
        for (int q = 0; q < 4; q++) {
            ulonglong2 ia[4], ib[4];   // dup input pairs
            #pragma unroll
            for (int p = 0; p < 4; p++) {
                ia[p] = *(const ulonglong2*)(base[p] + off + q * 8);
                ib[p] = *(const ulonglong2*)(base[p] + off + q * 8 + 4);
            }
            const float* wbase = &sw[(k * 16 + q * 4) * 32 + cg * 16];
            #pragma unroll
            for (int cc = 0; cc < 4; cc++) {
                const ulonglong2* wp = (const ulonglong2*)(wbase + cc * 32);
                ulonglong2 w0 = wp[0], w1 = wp[1], w2 = wp[2], w3 = wp[3];
                #pragma unroll
                for (int p = 0; p < 4; p++) {
                    u64t vd = cc == 0 ? ia[p].x : cc == 1 ? ia[p].y
                            : cc == 2 ? ib[p].x : ib[p].y;
                    fma2(acc[p][0], vd, w0.x); fma2(acc[p][1], vd, w0.y);
                    fma2(acc[p][2], vd, w1.x); fma2(acc[p][3], vd, w1.y);
                    fma2(acc[p][4], vd, w2.x); fma2(acc[p][5], vd, w2.y);
                    fma2(acc[p][6], vd, w3.x); fma2(acc[p][7], vd, w3.y);
                }
            }
        }
    }
    #pragma unroll
    for (int p = 0; p < 4; p++) {
        if (pxv[p] < 484) {
            float4* op = (float4*)&g_c2[(size_t)img*C2_IMG + (size_t)pxv[p]*32 + cg*16];
            #pragma unroll
            for (int g = 0; g < 4; g++) {
                float a0, a1, a2, a3;
                upk2(a0, a1, acc[p][2*g]); upk2(a2, a3, acc[p][2*g+1]);
                float4 v;
                v.x = fmaxf(a0, 0.f); v.y = fmaxf(a1, 0.f);
                v.z = fmaxf(a2, 0.f); v.w = fmaxf(a3, 0.f);
                op[g] = v;
            }
        }
    }
}

// ---------------- conv3: 32ch 22x22 -> 64ch 21x21 ----------------
#define C3ISTR 36
__global__ void __launch_bounds__(256) k_conv3(const float* __restrict__ w3,
                                               const float* __restrict__ b3)
{
    extern __shared__ float sm[];
    float* si = sm;                // 484*36 = 17424 floats
    float* sw = sm + 484*C3ISTR;   // 8192 floats (69696B offset, aligned)
    int img = blockIdx.x, tid = threadIdx.x;
    const float4* in4 = (const float4*)&g_c2[(size_t)img*C2_IMG];
    for (int i4 = tid; i4 < 484*8; i4 += 256) {
        int px = i4 >> 3, c4 = i4 & 7;
        *(float4*)&si[px*C3ISTR + c4*4] = in4[i4];
    }
    for (int i = tid; i < 8192; i += 256) sw[i] = w3[i];
    int cg = tid >> 6, ps = tid & 63;
    u64t bias[8];
    #pragma unroll
    for (int j = 0; j < 8; j++) bias[j] = pk2(b3[cg*16 + 2*j], b3[cg*16 + 2*j + 1]);
    __syncthreads();

    float* out = g_feat + (size_t)img*FEATD;
    conv2x2_block<4, 8, 64, C3ISTR, 22, 21, 441>(si, sw, bias, out, cg, ps, 64);
    conv2x2_block<3, 8, 64, C3ISTR, 22, 21, 441>(si, sw, bias, out, cg, 256 + ps, 64);
}

// ---------------- big GEMM: IG = feat @ Wi^T (split-K=3 partials) ---------
__global__ void __launch_bounds__(128, 3) k_gemm(const float* __restrict__ Wi)
{
    extern __shared__ float sm[];
    float* As  = sm;                  // 2 * 32 * 132
    float* Bsd = sm + 2*GBK*GMS;      // 2 * 32 * 132 (33792B offset, aligned)
    int tid = threadIdx.x;
    int m0 = blockIdx.x * GBM, n0 = blockIdx.y * GBN, z = blockIdx.z;
    const float* Aptr = g_feat + (size_t)m0*FEATD + (size_t)z*KPART;
    const float* Bptr = Wi     + (size_t)n0*FEATD + (size_t)z*KPART;

    int tx = tid & 15, ty = tid >> 4;          // compute map (16 x 8)
    int bn_f = tid & 63, bq = (tid >> 6) * 16; // B fill: k base

    float4 pa[8], pb[4];
    u64t acc[8][4];                            // [n][m-chunk]
    #pragma unroll
    for (int j = 0; j < 8; j++)
        #pragma unroll
        for (int c = 0; c < 4; c++) acc[j][c] = 0ull;

    // prologue: load + store tile 0
    {
        const float* ap = Aptr + (size_t)tid*FEATD;
        #pragma unroll
        for (int q = 0; q < 8; q++) pa[q] = *(const float4*)(ap + q*4);
        const float* bp = Bptr + (size_t)bn_f*FEATD + bq;
        #pragma unroll
        for (int q = 0; q < 4; q++) pb[q] = *(const float4*)(bp + q*4);
    }
    {
        #pragma unroll
        for (int q = 0; q < 8; q++) {
            As[(q*4+0)*GMS + tid] = pa[q].x;
            As[(q*4+1)*GMS + tid] = pa[q].y;
            As[(q*4+2)*GMS + tid] = pa[q].z;
            As[(q*4+3)*GMS + tid] = pa[q].w;
        }
        #pragma unroll
        for (int q = 0; q < 4; q++) {
            float v0 = pb[q].x, v1 = pb[q].y, v2 = pb[q].z, v3 = pb[q].w;
            *(float2*)&Bsd[(bq+q*4+0)*GMS + 2*bn_f] = make_float2(v0, v0);
            *(float2*)&Bsd[(bq+q*4+1)*GMS + 2*bn_f] = make_float2(v1, v1);
            *(float2*)&Bsd[(bq+q*4+2)*GMS + 2*bn_f] = make_float2(v2, v2);
            *(float2*)&Bsd[(bq+q*4+3)*GMS + 2*bn_f] = make_float2(v3, v3);
        }
    }
    __syncthreads();

    for (int kt = 0; kt < NKITER; kt++) {
        int cur = kt & 1;
        if (kt + 1 < NKITER) {
            const float* ap = Aptr + (size_t)(kt+1)*GBK + (size_t)tid*FEATD;
            #pragma unroll
            for (int q = 0; q < 8; q++) pa[q] = *(const float4*)(ap + q*4);
            const float* bp = Bptr + (size_t)(kt+1)*GBK + (size_t)bn_f*FEATD + bq;
            #pragma unroll
            for (int q = 0; q < 4; q++) pb[q] = *(const float4*)(bp + q*4);
        }
        const float* A_ = As  + cur*GBK*GMS;
        const float* B_ = Bsd + cur*GBK*GMS;
        #pragma unroll 16
        for (int kk = 0; kk < GBK; kk++) {
            ulonglong2 a0 = *(const ulonglong2*)(A_ + kk*GMS + tx*4);
            ulonglong2 a1 = *(const ulonglong2*)(A_ + kk*GMS + 64 + tx*4);
            ulonglong2 b0 = *(const ulonglong2*)(B_ + kk*GMS + ty*16);
            ulonglong2 b1 = *(const ulonglong2*)(B_ + kk*GMS + ty*16 + 4);
            ulonglong2 b2 = *(const ulonglong2*)(B_ + kk*GMS + ty*16 + 8);
            ulonglong2 b3 = *(const ulonglong2*)(B_ + kk*GMS + ty*16 + 12);
            fma2(acc[0][0], a0.x, b0.x); fma2(acc[0][1], a0.y, b0.x);
            fma2(acc[0][2], a1.x, b0.x); fma2(acc[0][3], a1.y, b0.x);
            fma2(acc[1][0], a0.x, b0.y); fma2(acc[1][1], a0.y, b0.y);
            fma2(acc[1][2], a1.x, b0.y); fma2(acc[1][3], a1.y, b0.y);
            fma2(acc[2][0], a0.x, b1.x); fma2(acc[2][1], a0.y, b1.x);
            fma2(acc[2][2], a1.x, b1.x); fma2(acc[2][3], a1.y, b1.x);
            fma2(acc[3][0], a0.x, b1.y); fma2(acc[3][1], a0.y, b1.y);
            fma2(acc[3][2], a1.x, b1.y); fma2(acc[3][3], a1.y, b1.y);
            fma2(acc[4][0], a0.x, b2.x); fma2(acc[4][1], a0.y, b2.x);
            fma2(acc[4][2], a1.x, b2.x); fma2(acc[4][3], a1.y, b2.x);
            fma2(acc[5][0], a0.x, b2.y); fma2(acc[5][1], a0.y, b2.y);
            fma2(acc[5][2], a1.x, b2.y); fma2(acc[5][3], a1.y, b2.y);
            fma2(acc[6][0], a0.x, b3.x); fma2(acc[6][1], a0.y, b3.x);
            fma2(acc[6][2], a1.x, b3.x); fma2(acc[6][3], a1.y, b3.x);
            fma2(acc[7][0], a0.x, b3.y); fma2(acc[7][1], a0.y, b3.y);
            fma2(acc[7][2], a1.x, b3.y); fma2(acc[7][3], a1.y, b3.y);
        }
        if (kt + 1 < NKITER) {
            int nxt = cur ^ 1;
            float* A_n = As  + nxt*GBK*GMS;
            float* B_n = Bsd + nxt*GBK*GMS;
            #pragma unroll
            for (int q = 0; q < 8; q++) {
                A_n[(q*4+0)*GMS + tid] = pa[q].x;
                A_n[(q*4+1)*GMS + tid] = pa[q].y;
                A_n[(q*4+2)*GMS + tid] = pa[q].z;
                A_n[(q*4+3)*GMS + tid] = pa[q].w;
            }
            #pragma unroll
            for (int q = 0; q < 4; q++) {
                float v0 = pb[q].x, v1 = pb[q].y, v2 = pb[q].z, v3 = pb[q].w;
                *(float2*)&B_n[(bq+q*4+0)*GMS + 2*bn_f] = make_float2(v0, v0);
                *(float2*)&B_n[(bq+q*4+1)*GMS + 2*bn_f] = make_float2(v1, v1);
                *(float2*)&B_n[(bq+q*4+2)*GMS + 2*bn_f] = make_float2(v2, v2);
                *(float2*)&B_n[(bq+q*4+3)*GMS + 2*bn_f] = make_float2(v3, v3);
            }
            __syncthreads();
        }
    }

    // epilogue: m rows = {m0+tx*4+0..3, m0+64+tx*4+0..3}, n = n0+ty*8+0..7
    float o[8][8];
    #pragma unroll
    for (int j = 0; j < 8; j++) {
        upk2(o[0][j], o[1][j], acc[j][0]);
        upk2(o[2][j], o[3][j], acc[j][1]);
        upk2(o[4][j], o[5][j], acc[j][2]);
        upk2(o[6][j], o[7][j], acc[j][3]);
    }
    float* op = &g_igp[z][0];
    #pragma unroll
    for (int mi = 0; mi < 8; mi++) {
        int m = m0 + (mi < 4 ? tx*4 + mi : 64 + tx*4 + (mi - 4));
        float* dst = &op[(size_t)m*G3 + n0 + ty*8];
        *(float4*)dst       = make_float4(o[mi][0], o[mi][1], o[mi][2], o[mi][3]);
        *(float4*)(dst + 4) = make_float4(o[mi][4], o[mi][5], o[mi][6], o[mi][7]);
    }
}

// ---------------- GRU scan: 32 blocks (one per batch row) ----------------
__global__ void __launch_bounds__(192) k_scan(
    const float* __restrict__ Wh, const float* __restrict__ bi,
    const float* __restrict__ bn, const float* __restrict__ h0,
    float* __restrict__ out_hidden)
{
    extern __shared__ float sWhT[];   // 64*192, WhT[d*192+n]
    __shared__ float sh[64], shg[192], sig[192], sbi[192], sbn[64];
    int b = blockIdx.x, tid = threadIdx.x;
    for (int i = tid; i < 64*G3; i += 192) {
        int d = i / G3, n = i - d*G3;
        sWhT[i] = Wh[n*64 + d];
    }
    sbi[tid] = bi[tid];
    if (tid < 64) { sbn[tid] = bn[tid]; sh[tid] = h0[b*64 + tid]; }
    __syncthreads();

    for (int t = 0; t < SEQ; t++) {
        size_t idx = (size_t)(b*SEQ + t)*G3 + tid;
        float ps = g_igp[0][idx] + g_igp[1][idx] + g_igp[2][idx];
        float acc = 0.f;
        #pragma unroll
        for (int d = 0; d < 64; d++) acc = fmaf(sh[d], sWhT[d*G3 + tid], acc);
        shg[tid] = acc;
        sig[tid] = ps + sbi[tid];
        __syncthreads();
        if (tid < 64) {
            float r  = 1.f / (1.f + expf(-(sig[tid]       + shg[tid])));
            float zz = 1.f / (1.f + expf(-(sig[64 + tid]  + shg[64 + tid])));
            float nn = tanhf(sig[128 + tid] + r * (shg[128 + tid] + sbn[tid]));
            float h  = (1.f - zz) * nn + zz * sh[tid];
            sh[tid] = h;
            g_allh[(size_t)(b*SEQ + t)*64 + tid] = h;
        }
        __syncthreads();
    }
    if (tid < 64) out_hidden[b*64 + tid] = sh[tid];
}

// ---------------- output heads ----------------
__global__ void __launch_bounds__(128) k_head(
    const float* __restrict__ Wa1, const float* __restrict__ ba1,
    const float* __restrict__ Wa2, const float* __restrict__ ba2,
    const float* __restrict__ Wc1, const float* __restrict__ bc1,
    const float* __restrict__ Wc2, const float* __restrict__ bc2,
    float* __restrict__ out_logits, float* __restrict__ out_values)
{
    __shared__ float sh[64], sa[64], sc[64];
    int row = blockIdx.x, tid = threadIdx.x;
    if (tid < 64) sh[tid] = g_allh[(size_t)row*64 + tid];
    __syncthreads();
    if (tid < 64) {
        float a = ba1[tid], c = bc1[tid];
        #pragma unroll
        for (int d = 0; d < 64; d++) {
            float h = sh[d];
            a = fmaf(h, Wa1[d*64 + tid], a);
            c = fmaf(h, Wc1[d*64 + tid], c);
        }
        sa[tid] = tanhf(a);
        sc[tid] = tanhf(c);
    }
    __syncthreads();
    if (tid < 96) {
        float l = ba2[tid];
        #pragma unroll
        for (int j = 0; j < 64; j++) l = fmaf(sa[j], Wa2[j*96 + tid], l);
        out_logits[(size_t)row*96 + tid] = l;
    } else {
        int d = tid - 96;
        float v = sc[d]*Wc2[d] + sc[d+32]*Wc2[d+32];
        #pragma unroll
        for (int o = 16; o > 0; o >>= 1) v += __shfl_xor_sync(0xffffffffu, v, o);
        if (d == 0) out_values[row] = v + bc2[0];
    }
}

// ---------------- launch ----------------
extern "C" void kernel_launch(void* const* d_in, const int* in_sizes, int n_in,
                              void* d_out, int out_size)
{
    const int*   positions       = (const int*)  d_in[0];
    const void*  units_mask      =               d_in[1];
    const int*   tile_type       = (const int*)  d_in[2];
    const int*   relic_positions = (const int*)  d_in[3];
    const void*  relic_mask      =               d_in[4];
    const float* reward          = (const float*)d_in[5];
    const float* hidden          = (const float*)d_in[6];
    const float* emb_tile        = (const float*)d_in[7];
    const float* emb_unit        = (const float*)d_in[8];
    const float* w1 = (const float*)d_in[9];
    const float* b1 = (const float*)d_in[10];
    const float* w2 = (const float*)d_in[11];
    const float* b2 = (const float*)d_in[12];
    const float* w3 = (const float*)d_in[13];
    const float* b3 = (const float*)d_in[14];
    const float* Wi = (const float*)d_in[15];
    const float* Wh = (const float*)d_in[16];
    const float* bi = (const float*)d_in[17];
    const float* bn = (const float*)d_in[18];
    const float* Wa1 = (const float*)d_in[19];
    const float* ba1 = (const float*)d_in[20];
    const float* Wa2 = (const float*)d_in[21];
    const float* ba2 = (const float*)d_in[22];
    const float* Wc1 = (const float*)d_in[23];
    const float* bc1 = (const float*)d_in[24];
    const float* Wc2 = (const float*)d_in[25];
    const float* bc2 = (const float*)d_in[26];

    float* out        = (float*)d_out;
    float* out_logits = out;                       // 4096*96
    float* out_values = out + 393216;              // 4096
    float* out_hidden = out + 393216 + 4096;       // 2048

    const int smem_gc1  = (576*G1STR + 1536) * 4;       // 70656
    const int smem_c2   = (529*C2ISTR + 2048) * 4;      // 84368
    const int smem_c3   = (484*C3ISTR + 8192) * 4;      // 102464
    const int smem_gemm = (4*GBK*GMS) * 4;              // 67584
    const int smem_scan = 64*G3*4;                      // 49152

    cudaFuncSetAttribute(k_grid_conv1, cudaFuncAttributeMaxDynamicSharedMemorySize, smem_gc1);
    cudaFuncSetAttribute(k_conv2,      cudaFuncAttributeMaxDynamicSharedMemorySize, smem_c2);
    cudaFuncSetAttribute(k_conv3,      cudaFuncAttributeMaxDynamicSharedMemorySize, smem_c3);
    cudaFuncSetAttribute(k_gemm,       cudaFuncAttributeMaxDynamicSharedMemorySize, smem_gemm);
    cudaFuncSetAttribute(k_scan,       cudaFuncAttributeMaxDynamicSharedMemorySize, smem_scan);

    k_masks<<<1, 256>>>(units_mask, relic_mask);

    k_grid_conv1<<<NIMG, 256, smem_gc1>>>(positions, tile_type, relic_positions,
                                          reward, emb_tile, emb_unit, w1, b1);
    k_conv2<<<NIMG, 256, smem_c2>>>(w2, b2);
    k_conv3<<<NIMG, 256, smem_c3>>>(w3, b3);

    dim3 gg(NIMG/GBM, G3/GBN, KSPLIT);
    k_gemm<<<gg, 128, smem_gemm>>>(Wi);

    k_scan<<<BATCH, 192, smem_scan>>>(Wh, bi, bn, hidden, out_hidden);
    k_head<<<NIMG, 128>>>(Wa1, ba1, Wa2, ba2, Wc1, bc1, Wc2, bc2,
                          out_logits, out_values);
}